// round 1
// baseline (speedup 1.0000x reference)
#include <cuda_runtime.h>
#include <math.h>

#define NN 40000
#define EE 320000
#define FIN 128
#define HH 4
#define CC 64
#define HC 256
#define OUTC 64
#define NBLK 160
#define ROWS_PER_BLK 250

// ---------------- scratch (static device globals; no runtime allocation) ----------------
__device__ int g_is64;
__device__ int g_deg[NN];
__device__ int g_rowstart[NN + 1];
__device__ int g_cursor[NN];
__device__ int g_eid[EE];
__device__ float g_h[(size_t)NN * HC];      // current layer pre-attention features h = X@W
__device__ float g_gat[(size_t)NN * HC];    // layer1 GAT output (pre-BN)
__device__ float g_l1[(size_t)NN * HC];     // layer1 post BN+ELU
__device__ float g_l2[(size_t)NN * HC];     // layer2 GAT output
__device__ float g_es[NN * HH];
__device__ float g_ed[NN * HH];
__device__ unsigned g_maxkey[NN * HH];
__device__ float g_denom[NN * HH];
__device__ float g_alpha[(size_t)EE * HH];
__device__ float g_bnpart[NBLK * HC * 2];
__device__ float g_bnscale[HC];
__device__ float g_bnshift[HC];

// ---------------- helpers ----------------
__device__ __forceinline__ unsigned fkey(float f) {
    unsigned b = __float_as_uint(f);
    return (b & 0x80000000u) ? ~b : (b | 0x80000000u);
}
__device__ __forceinline__ float funkey(unsigned k) {
    unsigned b = (k & 0x80000000u) ? (k & 0x7FFFFFFFu) : ~k;
    return __uint_as_float(b);
}
__device__ __forceinline__ int fetch_idx(const void* p, long long i) {
    if (g_is64) return (int)((const long long*)p)[i];
    return ((const int*)p)[i];
}

// Detect whether edge_index buffer is int64 (high words of first 64 entries all zero)
__global__ void detect_k(const unsigned* __restrict__ buf) {
    if (threadIdx.x == 0) {
        int any = 0;
        for (int i = 0; i < 64; i++) any |= (buf[2 * i + 1] != 0u);
        g_is64 = any ? 0 : 1;
    }
}

__global__ void zero_deg_k() {
    int i = blockIdx.x * blockDim.x + threadIdx.x;
    if (i < NN) g_deg[i] = 0;
}
__global__ void zero_nh_k() {
    int i = blockIdx.x * blockDim.x + threadIdx.x;
    if (i < NN * HH) { g_maxkey[i] = 0u; g_denom[i] = 0.f; }
}

__global__ void count_k(const void* __restrict__ idx) {
    int e = blockIdx.x * blockDim.x + threadIdx.x;
    if (e >= EE) return;
    int dst = fetch_idx(idx, (long long)EE + e);
    atomicAdd(&g_deg[dst], 1);
}

// Single-block exclusive scan of g_deg -> g_rowstart, g_cursor
__global__ void scan_k() {
    __shared__ int warp_sums[32];
    int t = threadIdx.x;               // 1024 threads
    int lane = t & 31, wid = t >> 5;
    int offset = 0;
    for (int base = 0; base < NN; base += 1024) {
        int i = base + t;
        int v = (i < NN) ? g_deg[i] : 0;
        int x = v;
        #pragma unroll
        for (int d = 1; d < 32; d <<= 1) {
            int y = __shfl_up_sync(0xFFFFFFFFu, x, d);
            if (lane >= d) x += y;
        }
        if (lane == 31) warp_sums[wid] = x;
        __syncthreads();
        if (wid == 0) {
            int s = warp_sums[lane];
            #pragma unroll
            for (int d = 1; d < 32; d <<= 1) {
                int y = __shfl_up_sync(0xFFFFFFFFu, s, d);
                if (lane >= d) s += y;
            }
            warp_sums[lane] = s;
        }
        __syncthreads();
        int prefix = (wid > 0) ? warp_sums[wid - 1] : 0;
        int incl = x + prefix;
        if (i < NN) {
            int ex = offset + incl - v;
            g_rowstart[i] = ex;
            g_cursor[i] = ex;
        }
        offset += warp_sums[31];
        __syncthreads();
    }
    if (t == 0) g_rowstart[NN] = offset;
}

__global__ void fill_k(const void* __restrict__ idx) {
    int e = blockIdx.x * blockDim.x + threadIdx.x;
    if (e >= EE) return;
    int dst = fetch_idx(idx, (long long)EE + e);
    int pos = atomicAdd(&g_cursor[dst], 1);
    g_eid[pos] = e;
}

// ---------------- SIMT fp32 GEMM: C[M,N] = A[M,K] @ B[K,N] (+bias) ----------------
// AMODE==1: A := max(A, A2) elementwise (fused JK-max). K % 16 == 0, N % 64 == 0.
template <int AMODE, int WITHBIAS>
__global__ __launch_bounds__(256)
void sgemm_k(const float* __restrict__ A, const float* __restrict__ A2,
             const float* __restrict__ B, const float* __restrict__ bias,
             float* __restrict__ C, int M, int N, int K) {
    constexpr int BM = 128, BN = 64, BK = 16;
    __shared__ float As[BK][BM + 1];
    __shared__ float Bs[BK][BN];
    int tid = threadIdx.x;
    int trow = tid >> 4;   // 0..15
    int tcol = tid & 15;   // 0..15
    int rowBase = blockIdx.y * BM;
    int colBase = blockIdx.x * BN;
    float acc[8][4] = {};

    for (int k0 = 0; k0 < K; k0 += BK) {
        #pragma unroll
        for (int l = 0; l < 2; l++) {
            int q = tid + l * 256;
            int ar = q >> 2;            // 0..127
            int ac = (q & 3) * 4;       // 0,4,8,12
            int grow = rowBase + ar;
            float4 v = make_float4(0.f, 0.f, 0.f, 0.f);
            if (grow < M) {
                v = *(const float4*)(A + (size_t)grow * K + k0 + ac);
                if (AMODE == 1) {
                    float4 w = *(const float4*)(A2 + (size_t)grow * K + k0 + ac);
                    v.x = fmaxf(v.x, w.x); v.y = fmaxf(v.y, w.y);
                    v.z = fmaxf(v.z, w.z); v.w = fmaxf(v.w, w.w);
                }
            }
            As[ac + 0][ar] = v.x; As[ac + 1][ar] = v.y;
            As[ac + 2][ar] = v.z; As[ac + 3][ar] = v.w;
        }
        {
            int br = tid >> 4;          // 0..15
            int bc = (tid & 15) * 4;    // 0..60
            float4 v = *(const float4*)(B + (size_t)(k0 + br) * N + colBase + bc);
            *(float4*)&Bs[br][bc] = v;
        }
        __syncthreads();
        #pragma unroll
        for (int kk = 0; kk < BK; kk++) {
            float aR[8], bR[4];
            #pragma unroll
            for (int i = 0; i < 8; i++) aR[i] = As[kk][trow * 8 + i];
            #pragma unroll
            for (int j = 0; j < 4; j++) bR[j] = Bs[kk][tcol * 4 + j];
            #pragma unroll
            for (int i = 0; i < 8; i++)
                #pragma unroll
                for (int j = 0; j < 4; j++)
                    acc[i][j] = fmaf(aR[i], bR[j], acc[i][j]);
        }
        __syncthreads();
    }
    #pragma unroll
    for (int i = 0; i < 8; i++) {
        int grow = rowBase + trow * 8 + i;
        if (grow < M) {
            int gcol = colBase + tcol * 4;
            float4 v;
            v.x = acc[i][0]; v.y = acc[i][1]; v.z = acc[i][2]; v.w = acc[i][3];
            if (WITHBIAS) {
                v.x += bias[gcol + 0]; v.y += bias[gcol + 1];
                v.z += bias[gcol + 2]; v.w += bias[gcol + 3];
            }
            *(float4*)(C + (size_t)grow * N + gcol) = v;
        }
    }
}

// ---------------- per-node attention scores: es/ed[n,h] = <h[n,h,:], a[h,:]> ----------------
__global__ __launch_bounds__(256)
void scores_k(const float* __restrict__ h, const float* __restrict__ asrc,
              const float* __restrict__ adst) {
    int warp = (blockIdx.x * blockDim.x + threadIdx.x) >> 5;
    int lane = threadIdx.x & 31;
    if (warp >= NN) return;
    const float* hp = h + (size_t)warp * HC;
    #pragma unroll
    for (int hh = 0; hh < HH; hh++) {
        float v0 = hp[hh * 64 + lane], v1 = hp[hh * 64 + lane + 32];
        float s = v0 * asrc[hh * 64 + lane] + v1 * asrc[hh * 64 + lane + 32];
        float d = v0 * adst[hh * 64 + lane] + v1 * adst[hh * 64 + lane + 32];
        #pragma unroll
        for (int o = 16; o > 0; o >>= 1) {
            s += __shfl_xor_sync(0xFFFFFFFFu, s, o);
            d += __shfl_xor_sync(0xFFFFFFFFu, d, o);
        }
        if (lane == 0) { g_es[warp * HH + hh] = s; g_ed[warp * HH + hh] = d; }
    }
}

__global__ void edge_max_k(const void* __restrict__ idx) {
    int e = blockIdx.x * blockDim.x + threadIdx.x;
    if (e >= EE) return;
    int src = fetch_idx(idx, e);
    int dst = fetch_idx(idx, (long long)EE + e);
    #pragma unroll
    for (int hh = 0; hh < HH; hh++) {
        float v = g_es[src * HH + hh] + g_ed[dst * HH + hh];
        v = (v < 0.f) ? 0.2f * v : v;
        atomicMax(&g_maxkey[dst * HH + hh], fkey(v));
    }
}

__global__ void edge_p_k(const void* __restrict__ idx) {
    int e = blockIdx.x * blockDim.x + threadIdx.x;
    if (e >= EE) return;
    int src = fetch_idx(idx, e);
    int dst = fetch_idx(idx, (long long)EE + e);
    #pragma unroll
    for (int hh = 0; hh < HH; hh++) {
        float v = g_es[src * HH + hh] + g_ed[dst * HH + hh];
        v = (v < 0.f) ? 0.2f * v : v;
        float m = funkey(g_maxkey[dst * HH + hh]);
        float p = expf(v - m);
        g_alpha[(size_t)e * HH + hh] = p;
        atomicAdd(&g_denom[dst * HH + hh], p);
    }
}

// one block per dst node; thread t owns channel t (head = t>>6); CSR loop, no atomics
__global__ __launch_bounds__(256)
void aggregate_k(const float* __restrict__ hfeat, const float* __restrict__ bias,
                 const void* __restrict__ idx, float* __restrict__ out) {
    int n = blockIdx.x;
    int t = threadIdx.x;
    int hh = t >> 6;
    int s = g_rowstart[n], en = g_rowstart[n + 1];
    float invd = 1.f / (g_denom[n * HH + hh] + 1e-16f);
    float acc = 0.f;
    for (int p = s; p < en; p++) {
        int eid = g_eid[p];
        int src = fetch_idx(idx, eid);
        float a = g_alpha[(size_t)eid * HH + hh] * invd;
        acc = fmaf(a, hfeat[(size_t)src * HC + t], acc);
    }
    out[(size_t)n * HC + t] = acc + bias[t];
}

// ---------------- BatchNorm (Kahan-compensated two-stage stats) ----------------
__global__ __launch_bounds__(256)
void bn_partial_k(const float* __restrict__ x) {
    int ch = threadIdx.x;
    int b = blockIdx.x;
    int r0 = b * ROWS_PER_BLK;
    int r1 = min(r0 + ROWS_PER_BLK, NN);
    float s = 0.f, cs = 0.f, q = 0.f, cq = 0.f;
    for (int r = r0; r < r1; r++) {
        float v = x[(size_t)r * HC + ch];
        float y = v - cs; float t = s + y; cs = (t - s) - y; s = t;
        float v2 = v * v;
        float y2 = v2 - cq; float t2 = q + y2; cq = (t2 - q) - y2; q = t2;
    }
    g_bnpart[b * 512 + ch] = s;
    g_bnpart[b * 512 + 256 + ch] = q;
}

__global__ void bn_final_k(const float* __restrict__ gamma, const float* __restrict__ beta) {
    int ch = threadIdx.x; // 256 threads
    float s = 0.f, cs = 0.f, q = 0.f, cq = 0.f;
    for (int b = 0; b < NBLK; b++) {
        float v = g_bnpart[b * 512 + ch];
        float y = v - cs; float t = s + y; cs = (t - s) - y; s = t;
        float v2 = g_bnpart[b * 512 + 256 + ch];
        float y2 = v2 - cq; float t2 = q + y2; cq = (t2 - q) - y2; q = t2;
    }
    float mean = s / (float)NN;
    float var = q / (float)NN - mean * mean;
    float sc = gamma[ch] * rsqrtf(var + 1e-5f);
    g_bnscale[ch] = sc;
    g_bnshift[ch] = beta[ch] - mean * sc;
}

__global__ void bn_apply_k(const float* __restrict__ x, float* __restrict__ y) {
    int i = blockIdx.x * blockDim.x + threadIdx.x;
    if (i >= NN * HC) return;
    int ch = i & (HC - 1);
    float v = x[i] * g_bnscale[ch] + g_bnshift[ch];
    y[i] = (v > 0.f) ? v : expm1f(v);
}

// ---------------- host side ----------------
static void run_layer(const float* X, int K, const float* W, const float* as_,
                      const float* ad_, const float* bias, float* gat_out,
                      const void* eidx, float* ph) {
    dim3 gg(HC / 64, (NN + 127) / 128);
    sgemm_k<0, 0><<<gg, 256>>>(X, nullptr, W, nullptr, ph, NN, HC, K);
    scores_k<<<(NN * 32 + 255) / 256, 256>>>(ph, as_, ad_);
    zero_nh_k<<<(NN * HH + 255) / 256, 256>>>();
    edge_max_k<<<(EE + 255) / 256, 256>>>(eidx);
    edge_p_k<<<(EE + 255) / 256, 256>>>(eidx);
    aggregate_k<<<NN, 256>>>(ph, bias, eidx, gat_out);
}

extern "C" void kernel_launch(void* const* d_in, const int* in_sizes, int n_in,
                              void* d_out, int out_size) {
    const float* x   = (const float*)d_in[0];
    const void*  eidx = d_in[1];
    const float* W1  = (const float*)d_in[2];
    const float* a1s = (const float*)d_in[3];
    const float* a1d = (const float*)d_in[4];
    const float* b1  = (const float*)d_in[5];
    const float* g1  = (const float*)d_in[6];
    const float* be1 = (const float*)d_in[7];
    const float* W2  = (const float*)d_in[8];
    const float* a2s = (const float*)d_in[9];
    const float* a2d = (const float*)d_in[10];
    const float* b2  = (const float*)d_in[11];
    const float* lW  = (const float*)d_in[12];
    const float* lb  = (const float*)d_in[13];
    float* out = (float*)d_out;

    float *ph, *pgat, *pl1, *pl2;
    cudaGetSymbolAddress((void**)&ph,   g_h);
    cudaGetSymbolAddress((void**)&pgat, g_gat);
    cudaGetSymbolAddress((void**)&pl1,  g_l1);
    cudaGetSymbolAddress((void**)&pl2,  g_l2);

    // graph preprocessing (must rerun every launch: deterministic, capture-safe)
    detect_k<<<1, 32>>>((const unsigned*)eidx);
    zero_deg_k<<<(NN + 255) / 256, 256>>>();
    count_k<<<(EE + 255) / 256, 256>>>(eidx);
    scan_k<<<1, 1024>>>();
    fill_k<<<(EE + 255) / 256, 256>>>(eidx);

    // layer 1: GAT(in=128 -> 4x64)
    run_layer(x, FIN, W1, a1s, a1d, b1, pgat, eidx, ph);
    // BN + ELU
    bn_partial_k<<<NBLK, 256>>>(pgat);
    bn_final_k<<<1, 256>>>(g1, be1);
    bn_apply_k<<<(NN * HC + 255) / 256, 256>>>(pgat, pl1);
    // layer 2: GAT(in=256 -> 4x64)
    run_layer(pl1, HC, W2, a2s, a2d, b2, pl2, eidx, ph);
    // JK max + final projection (fused)
    dim3 g3(OUTC / 64, (NN + 127) / 128);
    sgemm_k<1, 1><<<g3, 256>>>(pl1, pl2, lW, lb, out, NN, OUTC, HC);
}

// round 3
// speedup vs baseline: 1.3253x; 1.3253x over previous
#include <cuda_runtime.h>
#include <cuda_bf16.h>
#include <math.h>

#define NN 40000
#define EE 320000
#define FIN 128
#define HH 4
#define HC 256
#define OUTC 64
#define NBLK 160
#define ROWS_PER_BLK 250
#define SCB ((NN + 255) / 256)   // 157

// ---------------- scratch (static device globals) ----------------
__device__ int g_is64;
__device__ __align__(16) int g_src[EE];
__device__ __align__(16) int g_dst[EE];
__device__ int g_deg[NN];
__device__ int g_incl[SCB * 256];
__device__ int g_bsum[SCB];
__device__ int g_boff[SCB];
__device__ int g_rowstart[NN + 1];
__device__ int g_cursor[NN];
__device__ int g_eid[EE];
__device__ __align__(16) float g_h[(size_t)NN * HC];
__device__ __align__(16) float g_gat[(size_t)NN * HC];
__device__ __align__(16) float g_l1[(size_t)NN * HC];
__device__ __align__(16) float g_l2[(size_t)NN * HC];
__device__ __align__(16) float g_es[NN * HH];
__device__ __align__(16) float g_ed[NN * HH];
__device__ __align__(16) unsigned g_maxkey[NN * HH];
__device__ __align__(16) float g_denom[NN * HH];
__device__ __align__(16) float g_alpha[(size_t)EE * HH];
__device__ float g_bnpart[NBLK * HC * 2];
__device__ float g_bnscale[HC];
__device__ float g_bnshift[HC];
// transposed bf16 hi/lo weights [N,K]
__device__ __align__(16) __nv_bfloat16 g_w1t_hi[HC * FIN];
__device__ __align__(16) __nv_bfloat16 g_w1t_lo[HC * FIN];
__device__ __align__(16) __nv_bfloat16 g_w2t_hi[HC * HC];
__device__ __align__(16) __nv_bfloat16 g_w2t_lo[HC * HC];
__device__ __align__(16) __nv_bfloat16 g_w3t_hi[OUTC * HC];
__device__ __align__(16) __nv_bfloat16 g_w3t_lo[OUTC * HC];

// ---------------- small helpers ----------------
__device__ __forceinline__ unsigned fkey(float f) {
    unsigned b = __float_as_uint(f);
    return (b & 0x80000000u) ? ~b : (b | 0x80000000u);
}
__device__ __forceinline__ float funkey(unsigned k) {
    unsigned b = (k & 0x80000000u) ? (k & 0x7FFFFFFFu) : ~k;
    return __uint_as_float(b);
}
__device__ __forceinline__ unsigned smem_u32(const void* p) {
    unsigned r;
    asm("{ .reg .u64 t; cvta.to.shared.u64 t, %1; cvt.u32.u64 %0, t; }" : "=r"(r) : "l"(p));
    return r;
}
__device__ __forceinline__ unsigned pack2(float a, float b) {
    __nv_bfloat162 t = __floats2bfloat162_rn(a, b);
    return *reinterpret_cast<unsigned*>(&t);
}
__device__ __forceinline__ void ldsm4(unsigned* d, unsigned a) {
    asm volatile("ldmatrix.sync.aligned.m8n8.x4.shared.b16 {%0,%1,%2,%3}, [%4];"
                 : "=r"(d[0]), "=r"(d[1]), "=r"(d[2]), "=r"(d[3]) : "r"(a));
}
__device__ __forceinline__ void ldsm2(unsigned* d, unsigned a) {
    asm volatile("ldmatrix.sync.aligned.m8n8.x2.shared.b16 {%0,%1}, [%2];"
                 : "=r"(d[0]), "=r"(d[1]) : "r"(a));
}
__device__ __forceinline__ void mma16816(float* c, const unsigned* a, const unsigned* b) {
    asm volatile(
        "mma.sync.aligned.m16n8k16.row.col.f32.bf16.bf16.f32 "
        "{%0,%1,%2,%3}, {%4,%5,%6,%7}, {%8,%9}, {%0,%1,%2,%3};"
        : "+f"(c[0]), "+f"(c[1]), "+f"(c[2]), "+f"(c[3])
        : "r"(a[0]), "r"(a[1]), "r"(a[2]), "r"(a[3]), "r"(b[0]), "r"(b[1]));
}

// ---------------- preprocessing ----------------
__global__ void detect_k(const unsigned* __restrict__ buf) {
    if (threadIdx.x == 0) {
        int any = 0;
        for (int i = 0; i < 64; i++) any |= (buf[2 * i + 1] != 0u);
        g_is64 = any ? 0 : 1;
    }
}
__global__ void cvt_idx_k(const void* __restrict__ idx) {
    int e = blockIdx.x * blockDim.x + threadIdx.x;
    if (e >= EE) return;
    if (g_is64) {
        g_src[e] = (int)((const long long*)idx)[e];
        g_dst[e] = (int)((const long long*)idx)[(long long)EE + e];
    } else {
        g_src[e] = ((const int*)idx)[e];
        g_dst[e] = ((const int*)idx)[EE + e];
    }
}
__global__ void zero_deg_k() {
    int i = blockIdx.x * blockDim.x + threadIdx.x;
    if (i < NN) g_deg[i] = 0;
}
__global__ void count_k() {
    int e = blockIdx.x * blockDim.x + threadIdx.x;
    if (e < EE) atomicAdd(&g_deg[g_dst[e]], 1);
}
__global__ void scan1_k() {
    int t = threadIdx.x, b = blockIdx.x;
    int i = b * 256 + t;
    int v = (i < NN) ? g_deg[i] : 0;
    int lane = t & 31, w = t >> 5;
    int x = v;
    #pragma unroll
    for (int d = 1; d < 32; d <<= 1) {
        int y = __shfl_up_sync(0xFFFFFFFFu, x, d);
        if (lane >= d) x += y;
    }
    __shared__ int ws[8];
    if (lane == 31) ws[w] = x;
    __syncthreads();
    if (t == 0) {
        int s = 0;
        #pragma unroll
        for (int j = 0; j < 8; j++) { s += ws[j]; ws[j] = s; }
    }
    __syncthreads();
    int incl = x + (w ? ws[w - 1] : 0);
    if (i < NN) g_incl[i] = incl;
    if (t == 255) g_bsum[b] = incl;
}
__global__ void scan2_k() {
    int t = threadIdx.x;
    __shared__ int s[256];
    int v = (t < SCB) ? g_bsum[t] : 0;
    s[t] = v;
    __syncthreads();
    for (int d = 1; d < 256; d <<= 1) {
        int x = (t >= d) ? s[t - d] : 0;
        __syncthreads();
        s[t] += x;
        __syncthreads();
    }
    if (t < SCB) g_boff[t] = s[t] - v;
}
__global__ void scan3_k() {
    int i = blockIdx.x * 256 + threadIdx.x;
    if (i < NN) {
        int ex = g_incl[i] - g_deg[i] + g_boff[blockIdx.x];
        g_rowstart[i] = ex;
        g_cursor[i] = ex;
    }
    if (i == 0) g_rowstart[NN] = EE;
}
__global__ void fill_k() {
    int e = blockIdx.x * blockDim.x + threadIdx.x;
    if (e >= EE) return;
    int pos = atomicAdd(&g_cursor[g_dst[e]], 1);
    g_eid[pos] = e;
}

// ---------------- weight transpose + bf16 split ----------------
__global__ void wconv_k(const float* __restrict__ W, __nv_bfloat16* __restrict__ Thi,
                        __nv_bfloat16* __restrict__ Tlo, int K, int N) {
    int idx = blockIdx.x * blockDim.x + threadIdx.x;
    if (idx >= K * N) return;
    int k = idx / N, n = idx % N;
    float v = W[idx];
    __nv_bfloat16 h = __float2bfloat16_rn(v);
    float r = v - __bfloat162float(h);
    Thi[(size_t)n * K + k] = h;
    Tlo[(size_t)n * K + k] = __float2bfloat16_rn(r);
}

// ---------------- mma.sync split-bf16 GEMM ----------------
// C[M,NT] = A[M,KT] @ Bt^T; Bt is [NT,KT] bf16 hi/lo. 3-term: AhBh + AhBl + AlBh.
// Block tile 128x64, 8 warps (4 row x 2 col), warp tile 32x32 (2 m16 x 4 n8).
// JK==1: A := max(A, A2) elementwise, add bias in epilogue.
template <int KT, int NT, int JK>
__global__ __launch_bounds__(256)
void mma_gemm_k(const float* __restrict__ A, const float* __restrict__ A2,
                const __nv_bfloat16* __restrict__ Bhi, const __nv_bfloat16* __restrict__ Blo,
                const float* __restrict__ bias, float* __restrict__ C, int M) {
    __shared__ __align__(16) __nv_bfloat16 sA[2][128][40];  // [hi/lo][row][k], pad->80B rows
    __shared__ __align__(16) __nv_bfloat16 sB[2][64][40];
    int tid = threadIdx.x, lane = tid & 31, wid = tid >> 5;
    int wr = wid & 3, wc = wid >> 2;
    int rowBase = blockIdx.y * 128;
    int colBase = blockIdx.x * 64;
    float acc[2][4][4] = {};

    for (int k0 = 0; k0 < KT; k0 += 32) {
        // A tile: 128 rows x 32 fp32 -> hi/lo bf16
        #pragma unroll
        for (int it = 0; it < 4; it++) {
            int q = tid + it * 256;      // 0..1023
            int r = q >> 3;              // 0..127
            int cc = (q & 7) * 4;        // 0..28
            int grow = rowBase + r;
            float4 v = make_float4(0.f, 0.f, 0.f, 0.f);
            if (grow < M) {
                v = *(const float4*)(A + (size_t)grow * KT + k0 + cc);
                if (JK) {
                    float4 w = *(const float4*)(A2 + (size_t)grow * KT + k0 + cc);
                    v.x = fmaxf(v.x, w.x); v.y = fmaxf(v.y, w.y);
                    v.z = fmaxf(v.z, w.z); v.w = fmaxf(v.w, w.w);
                }
            }
            float hx = __bfloat162float(__float2bfloat16_rn(v.x));
            float hy = __bfloat162float(__float2bfloat16_rn(v.y));
            float hz = __bfloat162float(__float2bfloat16_rn(v.z));
            float hw = __bfloat162float(__float2bfloat16_rn(v.w));
            *(uint2*)&sA[0][r][cc] = make_uint2(pack2(hx, hy), pack2(hz, hw));
            *(uint2*)&sA[1][r][cc] =
                make_uint2(pack2(v.x - hx, v.y - hy), pack2(v.z - hz, v.w - hw));
        }
        // B tile: 64 rows x 32 bf16 (hi & lo)
        #pragma unroll
        for (int it = 0; it < 2; it++) {
            int q = tid + it * 256;      // 0..511
            int r = q >> 3;              // 0..63
            int cc = (q & 7) * 4;
            size_t gidx = (size_t)(colBase + r) * KT + k0 + cc;
            *(uint2*)&sB[0][r][cc] = *(const uint2*)(Bhi + gidx);
            *(uint2*)&sB[1][r][cc] = *(const uint2*)(Blo + gidx);
        }
        __syncthreads();
        #pragma unroll
        for (int kk = 0; kk < 32; kk += 16) {
            unsigned ah[2][4], al[2][4], bh[4][2], bl[4][2];
            #pragma unroll
            for (int mi = 0; mi < 2; mi++) {
                int row = wr * 32 + mi * 16 + (lane & 7) + ((lane & 8) ? 8 : 0);
                int col = kk + ((lane & 16) ? 8 : 0);
                ldsm4(ah[mi], smem_u32(&sA[0][row][col]));
                ldsm4(al[mi], smem_u32(&sA[1][row][col]));
            }
            #pragma unroll
            for (int ni = 0; ni < 4; ni++) {
                int row = wc * 32 + ni * 8 + (lane & 7);
                int col = kk + ((lane & 8) ? 8 : 0);
                ldsm2(bh[ni], smem_u32(&sB[0][row][col]));
                ldsm2(bl[ni], smem_u32(&sB[1][row][col]));
            }
            #pragma unroll
            for (int mi = 0; mi < 2; mi++)
                #pragma unroll
                for (int ni = 0; ni < 4; ni++) {
                    mma16816(acc[mi][ni], ah[mi], bh[ni]);
                    mma16816(acc[mi][ni], ah[mi], bl[ni]);
                    mma16816(acc[mi][ni], al[mi], bh[ni]);
                }
        }
        __syncthreads();
    }
    // epilogue
    #pragma unroll
    for (int mi = 0; mi < 2; mi++) {
        int grow0 = rowBase + wr * 32 + mi * 16 + (lane >> 2);
        int grow1 = grow0 + 8;
        #pragma unroll
        for (int ni = 0; ni < 4; ni++) {
            int gcol = colBase + wc * 32 + ni * 8 + (lane & 3) * 2;
            float2 v0 = make_float2(acc[mi][ni][0], acc[mi][ni][1]);
            float2 v1 = make_float2(acc[mi][ni][2], acc[mi][ni][3]);
            if (JK) {
                float b0 = bias[gcol], b1 = bias[gcol + 1];
                v0.x += b0; v0.y += b1; v1.x += b0; v1.y += b1;
            }
            if (grow0 < M) *(float2*)(C + (size_t)grow0 * NT + gcol) = v0;
            if (grow1 < M) *(float2*)(C + (size_t)grow1 * NT + gcol) = v1;
        }
    }
}

// ---------------- attention ----------------
__global__ __launch_bounds__(256)
void scores_k(const float* __restrict__ h, const float* __restrict__ asrc,
              const float* __restrict__ adst) {
    int warp = (blockIdx.x * blockDim.x + threadIdx.x) >> 5;
    int lane = threadIdx.x & 31;
    if (warp >= NN) return;
    const float* hp = h + (size_t)warp * HC;
    #pragma unroll
    for (int hh = 0; hh < HH; hh++) {
        float v0 = hp[hh * 64 + lane], v1 = hp[hh * 64 + lane + 32];
        float s = v0 * asrc[hh * 64 + lane] + v1 * asrc[hh * 64 + lane + 32];
        float d = v0 * adst[hh * 64 + lane] + v1 * adst[hh * 64 + lane + 32];
        #pragma unroll
        for (int o = 16; o > 0; o >>= 1) {
            s += __shfl_xor_sync(0xFFFFFFFFu, s, o);
            d += __shfl_xor_sync(0xFFFFFFFFu, d, o);
        }
        if (lane == 0) { g_es[warp * HH + hh] = s; g_ed[warp * HH + hh] = d; }
    }
    if (lane < HH) { g_maxkey[warp * HH + lane] = 0u; g_denom[warp * HH + lane] = 0.f; }
}
__global__ void edge_max_k() {
    int e = blockIdx.x * blockDim.x + threadIdx.x;
    if (e >= EE) return;
    int src = g_src[e], dst = g_dst[e];
    float4 es = *(const float4*)&g_es[src * 4];
    float4 ed = *(const float4*)&g_ed[dst * 4];
    float v0 = es.x + ed.x, v1 = es.y + ed.y, v2 = es.z + ed.z, v3 = es.w + ed.w;
    v0 = (v0 < 0.f) ? 0.2f * v0 : v0;
    v1 = (v1 < 0.f) ? 0.2f * v1 : v1;
    v2 = (v2 < 0.f) ? 0.2f * v2 : v2;
    v3 = (v3 < 0.f) ? 0.2f * v3 : v3;
    atomicMax(&g_maxkey[dst * 4 + 0], fkey(v0));
    atomicMax(&g_maxkey[dst * 4 + 1], fkey(v1));
    atomicMax(&g_maxkey[dst * 4 + 2], fkey(v2));
    atomicMax(&g_maxkey[dst * 4 + 3], fkey(v3));
}
__global__ void edge_p_k() {
    int e = blockIdx.x * blockDim.x + threadIdx.x;
    if (e >= EE) return;
    int src = g_src[e], dst = g_dst[e];
    float4 es = *(const float4*)&g_es[src * 4];
    float4 ed = *(const float4*)&g_ed[dst * 4];
    uint4 mk = *(const uint4*)&g_maxkey[dst * 4];
    float v0 = es.x + ed.x, v1 = es.y + ed.y, v2 = es.z + ed.z, v3 = es.w + ed.w;
    v0 = (v0 < 0.f) ? 0.2f * v0 : v0;
    v1 = (v1 < 0.f) ? 0.2f * v1 : v1;
    v2 = (v2 < 0.f) ? 0.2f * v2 : v2;
    v3 = (v3 < 0.f) ? 0.2f * v3 : v3;
    float4 p;
    p.x = expf(v0 - funkey(mk.x));
    p.y = expf(v1 - funkey(mk.y));
    p.z = expf(v2 - funkey(mk.z));
    p.w = expf(v3 - funkey(mk.w));
    *(float4*)&g_alpha[(size_t)e * 4] = p;
    atomicAdd(&g_denom[dst * 4 + 0], p.x);
    atomicAdd(&g_denom[dst * 4 + 1], p.y);
    atomicAdd(&g_denom[dst * 4 + 2], p.z);
    atomicAdd(&g_denom[dst * 4 + 3], p.w);
}
__global__ __launch_bounds__(256)
void aggregate_k(const float* __restrict__ hfeat, const float* __restrict__ bias,
                 float* __restrict__ out) {
    int n = blockIdx.x;
    int t = threadIdx.x;
    int hh = t >> 6;
    int s = g_rowstart[n], en = g_rowstart[n + 1];
    float invd = 1.f / (g_denom[n * HH + hh] + 1e-16f);
    float acc = 0.f;
    for (int p = s; p < en; p++) {
        int eid = g_eid[p];
        int src = g_src[eid];
        float a = g_alpha[(size_t)eid * HH + hh] * invd;
        acc = fmaf(a, hfeat[(size_t)src * HC + t], acc);
    }
    out[(size_t)n * HC + t] = acc + bias[t];
}

// ---------------- BatchNorm ----------------
__global__ __launch_bounds__(256)
void bn_partial_k(const float* __restrict__ x) {
    int ch = threadIdx.x;
    int b = blockIdx.x;
    int r0 = b * ROWS_PER_BLK;
    int r1 = min(r0 + ROWS_PER_BLK, NN);
    float s = 0.f, cs = 0.f, q = 0.f, cq = 0.f;
    for (int r = r0; r < r1; r++) {
        float v = x[(size_t)r * HC + ch];
        float y = v - cs; float t = s + y; cs = (t - s) - y; s = t;
        float v2 = v * v;
        float y2 = v2 - cq; float t2 = q + y2; cq = (t2 - q) - y2; q = t2;
    }
    g_bnpart[b * 512 + ch] = s;
    g_bnpart[b * 512 + 256 + ch] = q;
}
__global__ void bn_final_k(const float* __restrict__ gamma, const float* __restrict__ beta) {
    int ch = threadIdx.x;
    float s = 0.f, cs = 0.f, q = 0.f, cq = 0.f;
    for (int b = 0; b < NBLK; b++) {
        float v = g_bnpart[b * 512 + ch];
        float y = v - cs; float t = s + y; cs = (t - s) - y; s = t;
        float v2 = g_bnpart[b * 512 + 256 + ch];
        float y2 = v2 - cq; float t2 = q + y2; cq = (t2 - q) - y2; q = t2;
    }
    float mean = s / (float)NN;
    float var = q / (float)NN - mean * mean;
    float sc = gamma[ch] * rsqrtf(var + 1e-5f);
    g_bnscale[ch] = sc;
    g_bnshift[ch] = beta[ch] - mean * sc;
}
__global__ void bn_apply_k(const float* __restrict__ x, float* __restrict__ y) {
    int i = blockIdx.x * blockDim.x + threadIdx.x;
    if (i >= NN * HC) return;
    int ch = i & (HC - 1);
    float v = x[i] * g_bnscale[ch] + g_bnshift[ch];
    y[i] = (v > 0.f) ? v : expm1f(v);
}

// ---------------- host ----------------
#define GDM ((NN + 127) / 128)

extern "C" void kernel_launch(void* const* d_in, const int* in_sizes, int n_in,
                              void* d_out, int out_size) {
    const float* x   = (const float*)d_in[0];
    const void*  eidx = d_in[1];
    const float* W1  = (const float*)d_in[2];
    const float* a1s = (const float*)d_in[3];
    const float* a1d = (const float*)d_in[4];
    const float* b1  = (const float*)d_in[5];
    const float* g1  = (const float*)d_in[6];
    const float* be1 = (const float*)d_in[7];
    const float* W2  = (const float*)d_in[8];
    const float* a2s = (const float*)d_in[9];
    const float* a2d = (const float*)d_in[10];
    const float* b2  = (const float*)d_in[11];
    const float* lW  = (const float*)d_in[12];
    const float* lb  = (const float*)d_in[13];
    float* out = (float*)d_out;

    float *ph, *pgat, *pl1, *pl2;
    cudaGetSymbolAddress((void**)&ph,   g_h);
    cudaGetSymbolAddress((void**)&pgat, g_gat);
    cudaGetSymbolAddress((void**)&pl1,  g_l1);
    cudaGetSymbolAddress((void**)&pl2,  g_l2);
    __nv_bfloat16 *w1h, *w1l, *w2h, *w2l, *w3h, *w3l;
    cudaGetSymbolAddress((void**)&w1h, g_w1t_hi);
    cudaGetSymbolAddress((void**)&w1l, g_w1t_lo);
    cudaGetSymbolAddress((void**)&w2h, g_w2t_hi);
    cudaGetSymbolAddress((void**)&w2l, g_w2t_lo);
    cudaGetSymbolAddress((void**)&w3h, g_w3t_hi);
    cudaGetSymbolAddress((void**)&w3l, g_w3t_lo);

    // graph preprocessing
    detect_k<<<1, 32>>>((const unsigned*)eidx);
    cvt_idx_k<<<(EE + 255) / 256, 256>>>(eidx);
    zero_deg_k<<<SCB, 256>>>();
    count_k<<<(EE + 255) / 256, 256>>>();
    scan1_k<<<SCB, 256>>>();
    scan2_k<<<1, 256>>>();
    scan3_k<<<SCB, 256>>>();
    fill_k<<<(EE + 255) / 256, 256>>>();

    // weight conversion (transpose + bf16 split)
    wconv_k<<<(FIN * HC + 255) / 256, 256>>>(W1, w1h, w1l, FIN, HC);
    wconv_k<<<(HC * HC + 255) / 256, 256>>>(W2, w2h, w2l, HC, HC);
    wconv_k<<<(HC * OUTC + 255) / 256, 256>>>(lW, w3h, w3l, HC, OUTC);

    // layer 1
    {
        dim3 g(HC / 64, GDM);
        mma_gemm_k<FIN, HC, 0><<<g, 256>>>(x, nullptr, w1h, w1l, nullptr, ph, NN);
    }
    scores_k<<<(NN * 32 + 255) / 256, 256>>>(ph, a1s, a1d);
    edge_max_k<<<(EE + 255) / 256, 256>>>();
    edge_p_k<<<(EE + 255) / 256, 256>>>();
    aggregate_k<<<NN, 256>>>(ph, b1, pgat);

    // BN + ELU
    bn_partial_k<<<NBLK, 256>>>(pgat);
    bn_final_k<<<1, 256>>>(g1, be1);
    bn_apply_k<<<(NN * HC + 255) / 256, 256>>>(pgat, pl1);

    // layer 2
    {
        dim3 g(HC / 64, GDM);
        mma_gemm_k<HC, HC, 0><<<g, 256>>>(pl1, nullptr, w2h, w2l, nullptr, ph, NN);
    }
    scores_k<<<(NN * 32 + 255) / 256, 256>>>(ph, a2s, a2d);
    edge_max_k<<<(EE + 255) / 256, 256>>>();
    edge_p_k<<<(EE + 255) / 256, 256>>>();
    aggregate_k<<<NN, 256>>>(ph, b2, pl2);

    // JK max + final projection
    {
        dim3 g(OUTC / 64, GDM);
        mma_gemm_k<HC, OUTC, 1><<<g, 256>>>(pl1, pl2, w3h, w3l, lb, out, NN);
    }
}

// round 4
// speedup vs baseline: 1.4487x; 1.0931x over previous
#include <cuda_runtime.h>
#include <cuda_bf16.h>
#include <math.h>

#define NN 40000
#define EE 320000
#define FIN 128
#define HH 4
#define HC 256
#define OUTC 64
#define NBLK 160
#define ROWS_PER_BLK 250
#define SCB ((NN + 255) / 256)   // 157

// ---------------- scratch ----------------
__device__ int g_is64;
__device__ __align__(16) int g_src[EE];
__device__ __align__(16) int g_dst[EE];
__device__ int g_deg[NN];
__device__ int g_incl[SCB * 256];
__device__ int g_bsum[SCB];
__device__ int g_boff[SCB];
__device__ int g_rowstart[NN + 1];
__device__ int g_cursor[NN];
__device__ __align__(16) int g_csr_src[EE];
__device__ __align__(16) float g_h[(size_t)NN * HC];
__device__ __align__(16) float g_gat[(size_t)NN * HC];
__device__ __align__(16) float g_l1[(size_t)NN * HC];
__device__ __align__(16) float g_l2[(size_t)NN * HC];
__device__ __align__(16) float g_es[NN * HH];
__device__ __align__(16) float g_ed[NN * HH];
__device__ __align__(16) float g_alpha[(size_t)EE * HH];
__device__ float g_bnpart[NBLK * HC * 2];
__device__ float g_bnscale[HC];
__device__ float g_bnshift[HC];
__device__ __align__(16) __nv_bfloat16 g_w1t_hi[HC * FIN];
__device__ __align__(16) __nv_bfloat16 g_w1t_lo[HC * FIN];
__device__ __align__(16) __nv_bfloat16 g_w2t_hi[HC * HC];
__device__ __align__(16) __nv_bfloat16 g_w2t_lo[HC * HC];
__device__ __align__(16) __nv_bfloat16 g_w3t_hi[OUTC * HC];
__device__ __align__(16) __nv_bfloat16 g_w3t_lo[OUTC * HC];

// ---------------- helpers ----------------
__device__ __forceinline__ unsigned smem_u32(const void* p) {
    unsigned r;
    asm("{ .reg .u64 t; cvta.to.shared.u64 t, %1; cvt.u32.u64 %0, t; }" : "=r"(r) : "l"(p));
    return r;
}
__device__ __forceinline__ unsigned pack2(float a, float b) {
    __nv_bfloat162 t = __floats2bfloat162_rn(a, b);
    return *reinterpret_cast<unsigned*>(&t);
}
__device__ __forceinline__ void ldsm4(unsigned* d, unsigned a) {
    asm volatile("ldmatrix.sync.aligned.m8n8.x4.shared.b16 {%0,%1,%2,%3}, [%4];"
                 : "=r"(d[0]), "=r"(d[1]), "=r"(d[2]), "=r"(d[3]) : "r"(a));
}
__device__ __forceinline__ void mma16816(float* c, const unsigned* a, const unsigned* b) {
    asm volatile(
        "mma.sync.aligned.m16n8k16.row.col.f32.bf16.bf16.f32 "
        "{%0,%1,%2,%3}, {%4,%5,%6,%7}, {%8,%9}, {%0,%1,%2,%3};"
        : "+f"(c[0]), "+f"(c[1]), "+f"(c[2]), "+f"(c[3])
        : "r"(a[0]), "r"(a[1]), "r"(a[2]), "r"(a[3]), "r"(b[0]), "r"(b[1]));
}

// ---------------- preprocessing ----------------
__global__ void detect_k(const unsigned* __restrict__ buf) {
    if (threadIdx.x == 0) {
        int any = 0;
        for (int i = 0; i < 64; i++) any |= (buf[2 * i + 1] != 0u);
        g_is64 = any ? 0 : 1;
    }
}
// fused convert + degree count
__global__ void cvt_count_k(const void* __restrict__ idx) {
    int e = blockIdx.x * blockDim.x + threadIdx.x;
    if (e >= EE) return;
    int s, d;
    if (g_is64) {
        s = (int)((const long long*)idx)[e];
        d = (int)((const long long*)idx)[(long long)EE + e];
    } else {
        s = ((const int*)idx)[e];
        d = ((const int*)idx)[EE + e];
    }
    g_src[e] = s;
    g_dst[e] = d;
    atomicAdd(&g_deg[d], 1);
}
__global__ void scan1_k() {
    int t = threadIdx.x, b = blockIdx.x;
    int i = b * 256 + t;
    int v = (i < NN) ? g_deg[i] : 0;
    int lane = t & 31, w = t >> 5;
    int x = v;
    #pragma unroll
    for (int d = 1; d < 32; d <<= 1) {
        int y = __shfl_up_sync(0xFFFFFFFFu, x, d);
        if (lane >= d) x += y;
    }
    __shared__ int ws[8];
    if (lane == 31) ws[w] = x;
    __syncthreads();
    if (t == 0) {
        int s = 0;
        #pragma unroll
        for (int j = 0; j < 8; j++) { s += ws[j]; ws[j] = s; }
    }
    __syncthreads();
    int incl = x + (w ? ws[w - 1] : 0);
    if (i < NN) g_incl[i] = incl;
    if (t == 255) g_bsum[b] = incl;
}
__global__ void scan2_k() {
    int t = threadIdx.x;
    __shared__ int s[256];
    int v = (t < SCB) ? g_bsum[t] : 0;
    s[t] = v;
    __syncthreads();
    for (int d = 1; d < 256; d <<= 1) {
        int x = (t >= d) ? s[t - d] : 0;
        __syncthreads();
        s[t] += x;
        __syncthreads();
    }
    if (t < SCB) g_boff[t] = s[t] - v;
}
__global__ void scan3_k() {
    int i = blockIdx.x * 256 + threadIdx.x;
    if (i < NN) {
        int ex = g_incl[i] - g_deg[i] + g_boff[blockIdx.x];
        g_rowstart[i] = ex;
        g_cursor[i] = ex;
    }
    if (i == 0) g_rowstart[NN] = EE;
}
__global__ void fill_k() {
    int e = blockIdx.x * blockDim.x + threadIdx.x;
    if (e >= EE) return;
    int pos = atomicAdd(&g_cursor[g_dst[e]], 1);
    g_csr_src[pos] = g_src[e];
}

// ---------------- weight transpose + bf16 split ----------------
__global__ void wconv_k(const float* __restrict__ W, __nv_bfloat16* __restrict__ Thi,
                        __nv_bfloat16* __restrict__ Tlo, int K, int N) {
    int idx = blockIdx.x * blockDim.x + threadIdx.x;
    if (idx >= K * N) return;
    int k = idx / N, n = idx % N;
    float v = W[idx];
    __nv_bfloat16 h = __float2bfloat16_rn(v);
    float r = v - __bfloat162float(h);
    Thi[(size_t)n * K + k] = h;
    Tlo[(size_t)n * K + k] = __float2bfloat16_rn(r);
}

// ---------------- mma.sync split-bf16 GEMM ----------------
// Block tile 128 x NTILE, 8 warps (4 row x 2 col), warp tile 32 x NTILE/2.
template <int KT, int NT, int NTILE, int JK>
__global__ __launch_bounds__(256)
void mma_gemm_k(const float* __restrict__ A, const float* __restrict__ A2,
                const __nv_bfloat16* __restrict__ Bhi, const __nv_bfloat16* __restrict__ Blo,
                const float* __restrict__ bias, float* __restrict__ C, int M) {
    constexpr int NI = NTILE / 16;   // n8 groups per warp
    __shared__ __align__(16) __nv_bfloat16 sA[2][128][40];
    __shared__ __align__(16) __nv_bfloat16 sB[2][NTILE][40];
    int tid = threadIdx.x, lane = tid & 31, wid = tid >> 5;
    int wr = wid & 3, wc = wid >> 2;
    int rowBase = blockIdx.y * 128;
    int colBase = blockIdx.x * NTILE;
    float acc[2][NI][4] = {};

    for (int k0 = 0; k0 < KT; k0 += 32) {
        #pragma unroll
        for (int it = 0; it < 4; it++) {
            int q = tid + it * 256;
            int r = q >> 3;
            int cc = (q & 7) * 4;
            int grow = rowBase + r;
            float4 v = make_float4(0.f, 0.f, 0.f, 0.f);
            if (grow < M) {
                v = *(const float4*)(A + (size_t)grow * KT + k0 + cc);
                if (JK) {
                    float4 w = *(const float4*)(A2 + (size_t)grow * KT + k0 + cc);
                    v.x = fmaxf(v.x, w.x); v.y = fmaxf(v.y, w.y);
                    v.z = fmaxf(v.z, w.z); v.w = fmaxf(v.w, w.w);
                }
            }
            float hx = __bfloat162float(__float2bfloat16_rn(v.x));
            float hy = __bfloat162float(__float2bfloat16_rn(v.y));
            float hz = __bfloat162float(__float2bfloat16_rn(v.z));
            float hw = __bfloat162float(__float2bfloat16_rn(v.w));
            *(uint2*)&sA[0][r][cc] = make_uint2(pack2(hx, hy), pack2(hz, hw));
            *(uint2*)&sA[1][r][cc] =
                make_uint2(pack2(v.x - hx, v.y - hy), pack2(v.z - hz, v.w - hw));
        }
        #pragma unroll
        for (int it = 0; it < NTILE / 32; it++) {
            int q = tid + it * 256;
            int r = q >> 3;
            int cc = (q & 7) * 4;
            size_t gidx = (size_t)(colBase + r) * KT + k0 + cc;
            *(uint2*)&sB[0][r][cc] = *(const uint2*)(Bhi + gidx);
            *(uint2*)&sB[1][r][cc] = *(const uint2*)(Blo + gidx);
        }
        __syncthreads();
        #pragma unroll
        for (int kk = 0; kk < 32; kk += 16) {
            unsigned ah[2][4], al[2][4], bh[NI / 2][4], bl[NI / 2][4];
            #pragma unroll
            for (int mi = 0; mi < 2; mi++) {
                int row = wr * 32 + mi * 16 + (lane & 7) + ((lane & 8) ? 8 : 0);
                int col = kk + ((lane & 16) ? 8 : 0);
                ldsm4(ah[mi], smem_u32(&sA[0][row][col]));
                ldsm4(al[mi], smem_u32(&sA[1][row][col]));
            }
            #pragma unroll
            for (int nb = 0; nb < NI / 2; nb++) {
                int row = wc * (NTILE / 2) + nb * 16 + ((lane & 16) ? 8 : 0) + (lane & 7);
                int col = kk + ((lane & 8) ? 8 : 0);
                ldsm4(bh[nb], smem_u32(&sB[0][row][col]));
                ldsm4(bl[nb], smem_u32(&sB[1][row][col]));
            }
            #pragma unroll
            for (int mi = 0; mi < 2; mi++)
                #pragma unroll
                for (int nb = 0; nb < NI / 2; nb++) {
                    mma16816(acc[mi][2 * nb], ah[mi], &bh[nb][0]);
                    mma16816(acc[mi][2 * nb], ah[mi], &bl[nb][0]);
                    mma16816(acc[mi][2 * nb], al[mi], &bh[nb][0]);
                    mma16816(acc[mi][2 * nb + 1], ah[mi], &bh[nb][2]);
                    mma16816(acc[mi][2 * nb + 1], ah[mi], &bl[nb][2]);
                    mma16816(acc[mi][2 * nb + 1], al[mi], &bh[nb][2]);
                }
        }
        __syncthreads();
    }
    #pragma unroll
    for (int mi = 0; mi < 2; mi++) {
        int grow0 = rowBase + wr * 32 + mi * 16 + (lane >> 2);
        int grow1 = grow0 + 8;
        #pragma unroll
        for (int ni = 0; ni < NI; ni++) {
            int gcol = colBase + wc * (NTILE / 2) + ni * 8 + (lane & 3) * 2;
            float2 v0 = make_float2(acc[mi][ni][0], acc[mi][ni][1]);
            float2 v1 = make_float2(acc[mi][ni][2], acc[mi][ni][3]);
            if (JK) {
                float b0 = bias[gcol], b1 = bias[gcol + 1];
                v0.x += b0; v0.y += b1; v1.x += b0; v1.y += b1;
            }
            if (grow0 < M) *(float2*)(C + (size_t)grow0 * NT + gcol) = v0;
            if (grow1 < M) *(float2*)(C + (size_t)grow1 * NT + gcol) = v1;
        }
    }
}

// ---------------- attention ----------------
__global__ __launch_bounds__(256)
void scores_k(const float* __restrict__ h, const float* __restrict__ asrc,
              const float* __restrict__ adst) {
    int warp = (blockIdx.x * blockDim.x + threadIdx.x) >> 5;
    int lane = threadIdx.x & 31;
    if (warp >= NN) return;
    const float* hp = h + (size_t)warp * HC;
    #pragma unroll
    for (int hh = 0; hh < HH; hh++) {
        float v0 = hp[hh * 64 + lane], v1 = hp[hh * 64 + lane + 32];
        float s = v0 * asrc[hh * 64 + lane] + v1 * asrc[hh * 64 + lane + 32];
        float d = v0 * adst[hh * 64 + lane] + v1 * adst[hh * 64 + lane + 32];
        #pragma unroll
        for (int o = 16; o > 0; o >>= 1) {
            s += __shfl_xor_sync(0xFFFFFFFFu, s, o);
            d += __shfl_xor_sync(0xFFFFFFFFu, d, o);
        }
        if (lane == 0) { g_es[warp * HH + hh] = s; g_ed[warp * HH + hh] = d; }
    }
}

// warp-per-node CSR softmax; writes NORMALIZED alpha in CSR order (no atomics)
__global__ __launch_bounds__(256)
void softmax_k() {
    int wid = threadIdx.x >> 5, lane = threadIdx.x & 31;
    int n = blockIdx.x * 8 + wid;
    if (n >= NN) return;
    int s = g_rowstart[n], en = g_rowstart[n + 1];
    int deg = en - s;
    if (deg == 0) return;
    float4 ed = *(const float4*)&g_ed[n * 4];

    if (deg <= 32) {
        float v0 = -1e30f, v1 = -1e30f, v2 = -1e30f, v3 = -1e30f;
        if (lane < deg) {
            int src = g_csr_src[s + lane];
            float4 es = *(const float4*)&g_es[src * 4];
            v0 = es.x + ed.x; v0 = fmaxf(v0, 0.2f * v0);
            v1 = es.y + ed.y; v1 = fmaxf(v1, 0.2f * v1);
            v2 = es.z + ed.z; v2 = fmaxf(v2, 0.2f * v2);
            v3 = es.w + ed.w; v3 = fmaxf(v3, 0.2f * v3);
        }
        float m0 = v0, m1 = v1, m2 = v2, m3 = v3;
        #pragma unroll
        for (int o = 16; o > 0; o >>= 1) {
            m0 = fmaxf(m0, __shfl_xor_sync(0xFFFFFFFFu, m0, o));
            m1 = fmaxf(m1, __shfl_xor_sync(0xFFFFFFFFu, m1, o));
            m2 = fmaxf(m2, __shfl_xor_sync(0xFFFFFFFFu, m2, o));
            m3 = fmaxf(m3, __shfl_xor_sync(0xFFFFFFFFu, m3, o));
        }
        float p0 = 0.f, p1 = 0.f, p2 = 0.f, p3 = 0.f;
        if (lane < deg) {
            p0 = expf(v0 - m0); p1 = expf(v1 - m1);
            p2 = expf(v2 - m2); p3 = expf(v3 - m3);
        }
        float d0 = p0, d1 = p1, d2 = p2, d3 = p3;
        #pragma unroll
        for (int o = 16; o > 0; o >>= 1) {
            d0 += __shfl_xor_sync(0xFFFFFFFFu, d0, o);
            d1 += __shfl_xor_sync(0xFFFFFFFFu, d1, o);
            d2 += __shfl_xor_sync(0xFFFFFFFFu, d2, o);
            d3 += __shfl_xor_sync(0xFFFFFFFFu, d3, o);
        }
        if (lane < deg) {
            float4 a;
            a.x = p0 / (d0 + 1e-16f); a.y = p1 / (d1 + 1e-16f);
            a.z = p2 / (d2 + 1e-16f); a.w = p3 / (d3 + 1e-16f);
            *(float4*)&g_alpha[(size_t)(s + lane) * 4] = a;
        }
    } else {
        // generic 3-pass
        float m0 = -1e30f, m1 = -1e30f, m2 = -1e30f, m3 = -1e30f;
        for (int p = s + lane; p < en; p += 32) {
            int src = g_csr_src[p];
            float4 es = *(const float4*)&g_es[src * 4];
            float v0 = es.x + ed.x; v0 = fmaxf(v0, 0.2f * v0);
            float v1 = es.y + ed.y; v1 = fmaxf(v1, 0.2f * v1);
            float v2 = es.z + ed.z; v2 = fmaxf(v2, 0.2f * v2);
            float v3 = es.w + ed.w; v3 = fmaxf(v3, 0.2f * v3);
            m0 = fmaxf(m0, v0); m1 = fmaxf(m1, v1);
            m2 = fmaxf(m2, v2); m3 = fmaxf(m3, v3);
        }
        #pragma unroll
        for (int o = 16; o > 0; o >>= 1) {
            m0 = fmaxf(m0, __shfl_xor_sync(0xFFFFFFFFu, m0, o));
            m1 = fmaxf(m1, __shfl_xor_sync(0xFFFFFFFFu, m1, o));
            m2 = fmaxf(m2, __shfl_xor_sync(0xFFFFFFFFu, m2, o));
            m3 = fmaxf(m3, __shfl_xor_sync(0xFFFFFFFFu, m3, o));
        }
        float d0 = 0.f, d1 = 0.f, d2 = 0.f, d3 = 0.f;
        for (int p = s + lane; p < en; p += 32) {
            int src = g_csr_src[p];
            float4 es = *(const float4*)&g_es[src * 4];
            float v0 = es.x + ed.x; v0 = fmaxf(v0, 0.2f * v0);
            float v1 = es.y + ed.y; v1 = fmaxf(v1, 0.2f * v1);
            float v2 = es.z + ed.z; v2 = fmaxf(v2, 0.2f * v2);
            float v3 = es.w + ed.w; v3 = fmaxf(v3, 0.2f * v3);
            float4 a;
            a.x = expf(v0 - m0); a.y = expf(v1 - m1);
            a.z = expf(v2 - m2); a.w = expf(v3 - m3);
            d0 += a.x; d1 += a.y; d2 += a.z; d3 += a.w;
            *(float4*)&g_alpha[(size_t)p * 4] = a;
        }
        #pragma unroll
        for (int o = 16; o > 0; o >>= 1) {
            d0 += __shfl_xor_sync(0xFFFFFFFFu, d0, o);
            d1 += __shfl_xor_sync(0xFFFFFFFFu, d1, o);
            d2 += __shfl_xor_sync(0xFFFFFFFFu, d2, o);
            d3 += __shfl_xor_sync(0xFFFFFFFFu, d3, o);
        }
        float i0 = 1.f / (d0 + 1e-16f), i1 = 1.f / (d1 + 1e-16f);
        float i2 = 1.f / (d2 + 1e-16f), i3 = 1.f / (d3 + 1e-16f);
        for (int p = s + lane; p < en; p += 32) {
            float4 a = *(const float4*)&g_alpha[(size_t)p * 4];
            a.x *= i0; a.y *= i1; a.z *= i2; a.w *= i3;
            *(float4*)&g_alpha[(size_t)p * 4] = a;
        }
    }
}

// block-per-node aggregation, 4-way unrolled (MLP=4), alpha pre-normalized
__global__ __launch_bounds__(256)
void aggregate_k(const float* __restrict__ hfeat, const float* __restrict__ bias,
                 float* __restrict__ out) {
    int n = blockIdx.x;
    int t = threadIdx.x;
    int hh = t >> 6;
    int s = g_rowstart[n], en = g_rowstart[n + 1];
    float a0 = 0.f, a1 = 0.f, a2 = 0.f, a3 = 0.f;
    int p = s;
    for (; p + 4 <= en; p += 4) {
        int s0 = g_csr_src[p], s1 = g_csr_src[p + 1];
        int s2 = g_csr_src[p + 2], s3 = g_csr_src[p + 3];
        float w0 = g_alpha[(size_t)p * 4 + hh];
        float w1 = g_alpha[(size_t)(p + 1) * 4 + hh];
        float w2 = g_alpha[(size_t)(p + 2) * 4 + hh];
        float w3 = g_alpha[(size_t)(p + 3) * 4 + hh];
        a0 = fmaf(w0, hfeat[(size_t)s0 * HC + t], a0);
        a1 = fmaf(w1, hfeat[(size_t)s1 * HC + t], a1);
        a2 = fmaf(w2, hfeat[(size_t)s2 * HC + t], a2);
        a3 = fmaf(w3, hfeat[(size_t)s3 * HC + t], a3);
    }
    for (; p < en; p++) {
        int s0 = g_csr_src[p];
        float w0 = g_alpha[(size_t)p * 4 + hh];
        a0 = fmaf(w0, hfeat[(size_t)s0 * HC + t], a0);
    }
    out[(size_t)n * HC + t] = (a0 + a1) + (a2 + a3) + bias[t];
}

// ---------------- BatchNorm ----------------
__global__ __launch_bounds__(256)
void bn_partial_k(const float* __restrict__ x) {
    int ch = threadIdx.x;
    int b = blockIdx.x;
    int r0 = b * ROWS_PER_BLK;
    int r1 = min(r0 + ROWS_PER_BLK, NN);
    float s = 0.f, cs = 0.f, q = 0.f, cq = 0.f;
    for (int r = r0; r < r1; r++) {
        float v = x[(size_t)r * HC + ch];
        float y = v - cs; float t = s + y; cs = (t - s) - y; s = t;
        float v2 = v * v;
        float y2 = v2 - cq; float t2 = q + y2; cq = (t2 - q) - y2; q = t2;
    }
    g_bnpart[b * 512 + ch] = s;
    g_bnpart[b * 512 + 256 + ch] = q;
}
__global__ void bn_final_k(const float* __restrict__ gamma, const float* __restrict__ beta) {
    int ch = threadIdx.x;
    float s = 0.f, cs = 0.f, q = 0.f, cq = 0.f;
    for (int b = 0; b < NBLK; b++) {
        float v = g_bnpart[b * 512 + ch];
        float y = v - cs; float t = s + y; cs = (t - s) - y; s = t;
        float v2 = g_bnpart[b * 512 + 256 + ch];
        float y2 = v2 - cq; float t2 = q + y2; cq = (t2 - q) - y2; q = t2;
    }
    float mean = s / (float)NN;
    float var = q / (float)NN - mean * mean;
    float sc = gamma[ch] * rsqrtf(var + 1e-5f);
    g_bnscale[ch] = sc;
    g_bnshift[ch] = beta[ch] - mean * sc;
}
__global__ void bn_apply_k(const float* __restrict__ x, float* __restrict__ y) {
    int i = blockIdx.x * blockDim.x + threadIdx.x;
    if (i >= NN * HC) return;
    int ch = i & (HC - 1);
    float v = x[i] * g_bnscale[ch] + g_bnshift[ch];
    y[i] = (v > 0.f) ? v : expm1f(v);
}

// ---------------- host ----------------
#define GDM ((NN + 127) / 128)

extern "C" void kernel_launch(void* const* d_in, const int* in_sizes, int n_in,
                              void* d_out, int out_size) {
    const float* x   = (const float*)d_in[0];
    const void*  eidx = d_in[1];
    const float* W1  = (const float*)d_in[2];
    const float* a1s = (const float*)d_in[3];
    const float* a1d = (const float*)d_in[4];
    const float* b1  = (const float*)d_in[5];
    const float* g1  = (const float*)d_in[6];
    const float* be1 = (const float*)d_in[7];
    const float* W2  = (const float*)d_in[8];
    const float* a2s = (const float*)d_in[9];
    const float* a2d = (const float*)d_in[10];
    const float* b2  = (const float*)d_in[11];
    const float* lW  = (const float*)d_in[12];
    const float* lb  = (const float*)d_in[13];
    float* out = (float*)d_out;

    float *ph, *pgat, *pl1, *pl2;
    cudaGetSymbolAddress((void**)&ph,   g_h);
    cudaGetSymbolAddress((void**)&pgat, g_gat);
    cudaGetSymbolAddress((void**)&pl1,  g_l1);
    cudaGetSymbolAddress((void**)&pl2,  g_l2);
    __nv_bfloat16 *w1h, *w1l, *w2h, *w2l, *w3h, *w3l;
    cudaGetSymbolAddress((void**)&w1h, g_w1t_hi);
    cudaGetSymbolAddress((void**)&w1l, g_w1t_lo);
    cudaGetSymbolAddress((void**)&w2h, g_w2t_hi);
    cudaGetSymbolAddress((void**)&w2l, g_w2t_lo);
    cudaGetSymbolAddress((void**)&w3h, g_w3t_hi);
    cudaGetSymbolAddress((void**)&w3l, g_w3t_lo);
    int* pdeg;
    cudaGetSymbolAddress((void**)&pdeg, g_deg);

    cudaMemsetAsync(pdeg, 0, NN * sizeof(int));
    detect_k<<<1, 32>>>((const unsigned*)eidx);
    wconv_k<<<(FIN * HC + 255) / 256, 256>>>(W1, w1h, w1l, FIN, HC);
    wconv_k<<<(HC * HC + 255) / 256, 256>>>(W2, w2h, w2l, HC, HC);
    wconv_k<<<(HC * OUTC + 255) / 256, 256>>>(lW, w3h, w3l, HC, OUTC);
    cvt_count_k<<<(EE + 255) / 256, 256>>>(eidx);

    // layer 1 GEMM (slot ~5 for ncu)
    {
        dim3 g(HC / 128, GDM);
        mma_gemm_k<FIN, HC, 128, 0><<<g, 256>>>(x, nullptr, w1h, w1l, nullptr, ph, NN);
    }
    scan1_k<<<SCB, 256>>>();
    scan2_k<<<1, 256>>>();
    scan3_k<<<SCB, 256>>>();
    fill_k<<<(EE + 255) / 256, 256>>>();

    scores_k<<<(NN * 32 + 255) / 256, 256>>>(ph, a1s, a1d);
    softmax_k<<<(NN + 7) / 8, 256>>>();
    aggregate_k<<<NN, 256>>>(ph, b1, pgat);

    bn_partial_k<<<NBLK, 256>>>(pgat);
    bn_final_k<<<1, 256>>>(g1, be1);
    bn_apply_k<<<(NN * HC + 255) / 256, 256>>>(pgat, pl1);

    // layer 2
    {
        dim3 g(HC / 128, GDM);
        mma_gemm_k<HC, HC, 128, 0><<<g, 256>>>(pl1, nullptr, w2h, w2l, nullptr, ph, NN);
    }
    scores_k<<<(NN * 32 + 255) / 256, 256>>>(ph, a2s, a2d);
    softmax_k<<<(NN + 7) / 8, 256>>>();
    aggregate_k<<<NN, 256>>>(ph, b2, pl2);

    // JK max + final projection
    {
        dim3 g(OUTC / 64, GDM);
        mma_gemm_k<HC, OUTC, 64, 1><<<g, 256>>>(pl1, pl2, w3h, w3l, lb, out, NN);
    }
}

// round 5
// speedup vs baseline: 1.9607x; 1.3535x over previous
#include <cuda_runtime.h>
#include <cuda_bf16.h>
#include <math.h>

#define NN 40000
#define EE 320000
#define FIN 128
#define HH 4
#define HC 256
#define OUTC 64
#define NBLK 160
#define ROWS_PER_BLK 250
#define SCB ((NN + 255) / 256)   // 157

// ---------------- scratch ----------------
__device__ int g_is64;
__device__ __align__(16) int g_src[EE];
__device__ __align__(16) int g_dst[EE];
__device__ int g_deg[NN];
__device__ int g_incl[SCB * 256];
__device__ int g_bsum[SCB];
__device__ int g_boff[SCB];
__device__ int g_rowstart[NN + 1];
__device__ int g_cursor[NN];
__device__ __align__(16) int g_csr_src[EE];
__device__ __align__(16) float g_h[(size_t)NN * HC];
__device__ __align__(16) float g_gat[(size_t)NN * HC];
__device__ __align__(16) float g_l1[(size_t)NN * HC];
__device__ __align__(16) float g_l2[(size_t)NN * HC];
__device__ __align__(16) float g_es[NN * HH];
__device__ __align__(16) float g_ed[NN * HH];
__device__ __align__(16) float g_alpha[(size_t)EE * HH];
__device__ float g_bnpart[NBLK * HC * 2];
__device__ float g_bnscale[HC];
__device__ float g_bnshift[HC];
__device__ __align__(16) __nv_bfloat16 g_w1t_hi[HC * FIN];
__device__ __align__(16) __nv_bfloat16 g_w1t_lo[HC * FIN];
__device__ __align__(16) __nv_bfloat16 g_w2t_hi[HC * HC];
__device__ __align__(16) __nv_bfloat16 g_w2t_lo[HC * HC];
__device__ __align__(16) __nv_bfloat16 g_w3t_hi[OUTC * HC];
__device__ __align__(16) __nv_bfloat16 g_w3t_lo[OUTC * HC];

// ---------------- helpers ----------------
__device__ __forceinline__ unsigned smem_u32(const void* p) {
    unsigned r;
    asm("{ .reg .u64 t; cvta.to.shared.u64 t, %1; cvt.u32.u64 %0, t; }" : "=r"(r) : "l"(p));
    return r;
}
__device__ __forceinline__ unsigned pack2(float a, float b) {
    __nv_bfloat162 t = __floats2bfloat162_rn(a, b);
    return *reinterpret_cast<unsigned*>(&t);
}
__device__ __forceinline__ void ldsm4(unsigned* d, unsigned a) {
    asm volatile("ldmatrix.sync.aligned.m8n8.x4.shared.b16 {%0,%1,%2,%3}, [%4];"
                 : "=r"(d[0]), "=r"(d[1]), "=r"(d[2]), "=r"(d[3]) : "r"(a));
}
__device__ __forceinline__ void mma16816(float* c, const unsigned* a, const unsigned* b) {
    asm volatile(
        "mma.sync.aligned.m16n8k16.row.col.f32.bf16.bf16.f32 "
        "{%0,%1,%2,%3}, {%4,%5,%6,%7}, {%8,%9}, {%0,%1,%2,%3};"
        : "+f"(c[0]), "+f"(c[1]), "+f"(c[2]), "+f"(c[3])
        : "r"(a[0]), "r"(a[1]), "r"(a[2]), "r"(a[3]), "r"(b[0]), "r"(b[1]));
}
__device__ __forceinline__ void cp16(unsigned saddr, const void* gptr) {
    asm volatile("cp.async.cg.shared.global [%0], [%1], 16;" :: "r"(saddr), "l"(gptr));
}

// ---------------- preprocessing ----------------
__global__ void detect_k(const unsigned* __restrict__ buf) {
    if (threadIdx.x == 0) {
        int any = 0;
        for (int i = 0; i < 64; i++) any |= (buf[2 * i + 1] != 0u);
        g_is64 = any ? 0 : 1;
    }
}
__global__ void cvt_count_k(const void* __restrict__ idx) {
    int e = blockIdx.x * blockDim.x + threadIdx.x;
    if (e >= EE) return;
    int s, d;
    if (g_is64) {
        s = (int)((const long long*)idx)[e];
        d = (int)((const long long*)idx)[(long long)EE + e];
    } else {
        s = ((const int*)idx)[e];
        d = ((const int*)idx)[EE + e];
    }
    g_src[e] = s;
    g_dst[e] = d;
    atomicAdd(&g_deg[d], 1);
}
__global__ void scan1_k() {
    int t = threadIdx.x, b = blockIdx.x;
    int i = b * 256 + t;
    int v = (i < NN) ? g_deg[i] : 0;
    int lane = t & 31, w = t >> 5;
    int x = v;
    #pragma unroll
    for (int d = 1; d < 32; d <<= 1) {
        int y = __shfl_up_sync(0xFFFFFFFFu, x, d);
        if (lane >= d) x += y;
    }
    __shared__ int ws[8];
    if (lane == 31) ws[w] = x;
    __syncthreads();
    if (t == 0) {
        int s = 0;
        #pragma unroll
        for (int j = 0; j < 8; j++) { s += ws[j]; ws[j] = s; }
    }
    __syncthreads();
    int incl = x + (w ? ws[w - 1] : 0);
    if (i < NN) g_incl[i] = incl;
    if (t == 255) g_bsum[b] = incl;
}
__global__ void scan2_k() {
    int t = threadIdx.x;
    __shared__ int s[256];
    int v = (t < SCB) ? g_bsum[t] : 0;
    s[t] = v;
    __syncthreads();
    for (int d = 1; d < 256; d <<= 1) {
        int x = (t >= d) ? s[t - d] : 0;
        __syncthreads();
        s[t] += x;
        __syncthreads();
    }
    if (t < SCB) g_boff[t] = s[t] - v;
}
__global__ void scan3_k() {
    int i = blockIdx.x * 256 + threadIdx.x;
    if (i < NN) {
        int ex = g_incl[i] - g_deg[i] + g_boff[blockIdx.x];
        g_rowstart[i] = ex;
        g_cursor[i] = ex;
    }
    if (i == 0) g_rowstart[NN] = EE;
}
__global__ void fill_k() {
    int e = blockIdx.x * blockDim.x + threadIdx.x;
    if (e >= EE) return;
    int pos = atomicAdd(&g_cursor[g_dst[e]], 1);
    g_csr_src[pos] = g_src[e];
}

// ---------------- merged weight transpose + bf16 split (one launch) ----------------
__global__ void wconv_all_k(const float* __restrict__ W1, const float* __restrict__ W2,
                            const float* __restrict__ W3) {
    int gid = blockIdx.x * blockDim.x + threadIdx.x;
    const float* W;
    __nv_bfloat16 *Thi, *Tlo;
    int K, N, idx;
    if (gid < FIN * HC) {
        W = W1; Thi = g_w1t_hi; Tlo = g_w1t_lo; K = FIN; N = HC; idx = gid;
    } else if (gid < FIN * HC + HC * HC) {
        W = W2; Thi = g_w2t_hi; Tlo = g_w2t_lo; K = HC; N = HC; idx = gid - FIN * HC;
    } else if (gid < FIN * HC + HC * HC + HC * OUTC) {
        W = W3; Thi = g_w3t_hi; Tlo = g_w3t_lo; K = HC; N = OUTC;
        idx = gid - FIN * HC - HC * HC;
    } else return;
    int k = idx / N, n = idx % N;
    float v = W[idx];
    __nv_bfloat16 h = __float2bfloat16_rn(v);
    float r = v - __bfloat162float(h);
    Thi[(size_t)n * K + k] = h;
    Tlo[(size_t)n * K + k] = __float2bfloat16_rn(r);
}

// ---------------- pipelined mma.sync split-bf16 GEMM ----------------
// C[M,NT] = A @ Bt^T (Bt: [NT,KT] bf16 hi/lo). Double-buffered smem: cp.async for B,
// register prefetch + convert for A. 4 x WARPS_N warps, warp tile 32 x (NTILE/WARPS_N).
template <int KT, int NT, int NTILE, int WARPS_N, int JK>
__global__ __launch_bounds__(128 * WARPS_N)
void mma_gemm_k(const float* __restrict__ A, const float* __restrict__ A2,
                const __nv_bfloat16* __restrict__ Bhi, const __nv_bfloat16* __restrict__ Blo,
                const float* __restrict__ bias, float* __restrict__ C, int M) {
    constexpr int THREADS = 128 * WARPS_N;
    constexpr int WN = NTILE / WARPS_N;        // cols per warp
    constexpr int NI = WN / 8;                 // n8 groups per warp
    constexpr int LDA = 1024 / THREADS;        // float4 A loads per thread per chunk
    constexpr int LDB = 8 * NTILE / THREADS;   // 16B cp.async per thread per chunk
    constexpr int CH = KT / 32;
    constexpr unsigned ABUF = 20480;           // bytes per A buffer (2 x 128 x 40 x 2)
    constexpr unsigned BOFF = 2 * ABUF;
    constexpr unsigned BBUF = NTILE * 160;     // bytes per B buffer

    extern __shared__ char dynsm[];
    unsigned sbase = smem_u32(dynsm);
    int tid = threadIdx.x, lane = tid & 31, wid = tid >> 5;
    int wr = wid & 3, wc = wid >> 2;
    int rowBase = blockIdx.y * 128;
    int colBase = blockIdx.x * NTILE;
    float acc[2][NI][4] = {};
    float4 av[LDA], av2[LDA];

    auto loadA = [&](int c) {
        #pragma unroll
        for (int i = 0; i < LDA; i++) {
            int q = tid + i * THREADS;
            int r = q >> 3, cc = (q & 7) * 4;
            int grow = rowBase + r;
            av[i] = make_float4(0.f, 0.f, 0.f, 0.f);
            if (grow < M) {
                av[i] = *(const float4*)(A + (size_t)grow * KT + c * 32 + cc);
                if (JK) av2[i] = *(const float4*)(A2 + (size_t)grow * KT + c * 32 + cc);
                else av2[i] = make_float4(0.f, 0.f, 0.f, 0.f);
            } else av2[i] = make_float4(0.f, 0.f, 0.f, 0.f);
        }
    };
    auto storeA = [&](int buf) {
        #pragma unroll
        for (int i = 0; i < LDA; i++) {
            int q = tid + i * THREADS;
            int r = q >> 3, cc = (q & 7) * 4;
            float4 v = av[i];
            if (JK) {
                float4 w = av2[i];
                v.x = fmaxf(v.x, w.x); v.y = fmaxf(v.y, w.y);
                v.z = fmaxf(v.z, w.z); v.w = fmaxf(v.w, w.w);
            }
            float hx = __bfloat162float(__float2bfloat16_rn(v.x));
            float hy = __bfloat162float(__float2bfloat16_rn(v.y));
            float hz = __bfloat162float(__float2bfloat16_rn(v.z));
            float hw = __bfloat162float(__float2bfloat16_rn(v.w));
            unsigned off = buf * ABUF + (unsigned)(r * 40 + cc) * 2;
            *(uint2*)(dynsm + off) = make_uint2(pack2(hx, hy), pack2(hz, hw));
            *(uint2*)(dynsm + off + 10240) =
                make_uint2(pack2(v.x - hx, v.y - hy), pack2(v.z - hz, v.w - hw));
        }
    };
    auto loadB = [&](int c, int buf) {
        #pragma unroll
        for (int i = 0; i < LDB; i++) {
            int q = tid + i * THREADS;
            int hl = q / (4 * NTILE);
            int rem = q - hl * 4 * NTILE;
            int r = rem >> 2, seg = rem & 3;
            const __nv_bfloat16* src = hl ? Blo : Bhi;
            unsigned soff = BOFF + buf * BBUF + hl * (NTILE * 80) +
                            (unsigned)(r * 40 + seg * 8) * 2;
            cp16(sbase + soff, src + (size_t)(colBase + r) * KT + c * 32 + seg * 8);
        }
        asm volatile("cp.async.commit_group;");
    };
    auto compute = [&](int buf) {
        unsigned saA = sbase + buf * ABUF;
        unsigned saB = sbase + BOFF + buf * BBUF;
        #pragma unroll
        for (int kk = 0; kk < 32; kk += 16) {
            unsigned ah[2][4], al[2][4], bh[NI / 2][4], bl[NI / 2][4];
            #pragma unroll
            for (int mi = 0; mi < 2; mi++) {
                int row = wr * 32 + mi * 16 + (lane & 7) + ((lane & 8) ? 8 : 0);
                int col = kk + ((lane & 16) ? 8 : 0);
                ldsm4(ah[mi], saA + (unsigned)(row * 40 + col) * 2);
                ldsm4(al[mi], saA + 10240 + (unsigned)(row * 40 + col) * 2);
            }
            #pragma unroll
            for (int nb = 0; nb < NI / 2; nb++) {
                int row = wc * WN + nb * 16 + ((lane & 16) ? 8 : 0) + (lane & 7);
                int col = kk + ((lane & 8) ? 8 : 0);
                ldsm4(bh[nb], saB + (unsigned)(row * 40 + col) * 2);
                ldsm4(bl[nb], saB + (unsigned)(NTILE * 80) + (unsigned)(row * 40 + col) * 2);
            }
            #pragma unroll
            for (int mi = 0; mi < 2; mi++)
                #pragma unroll
                for (int nb = 0; nb < NI / 2; nb++) {
                    mma16816(acc[mi][2 * nb], ah[mi], &bh[nb][0]);
                    mma16816(acc[mi][2 * nb], ah[mi], &bl[nb][0]);
                    mma16816(acc[mi][2 * nb], al[mi], &bh[nb][0]);
                    mma16816(acc[mi][2 * nb + 1], ah[mi], &bh[nb][2]);
                    mma16816(acc[mi][2 * nb + 1], ah[mi], &bl[nb][2]);
                    mma16816(acc[mi][2 * nb + 1], al[mi], &bh[nb][2]);
                }
        }
    };

    // prologue
    loadB(0, 0);
    loadA(0);
    storeA(0);
    asm volatile("cp.async.wait_group 0;");
    __syncthreads();
    for (int c = 0; c < CH; c++) {
        int buf = c & 1;
        if (c + 1 < CH) { loadB(c + 1, buf ^ 1); loadA(c + 1); }
        compute(buf);
        if (c + 1 < CH) {
            storeA(buf ^ 1);
            asm volatile("cp.async.wait_group 0;");
        }
        __syncthreads();
    }
    // epilogue
    #pragma unroll
    for (int mi = 0; mi < 2; mi++) {
        int grow0 = rowBase + wr * 32 + mi * 16 + (lane >> 2);
        int grow1 = grow0 + 8;
        #pragma unroll
        for (int ni = 0; ni < NI; ni++) {
            int gcol = colBase + wc * WN + ni * 8 + (lane & 3) * 2;
            float2 v0 = make_float2(acc[mi][ni][0], acc[mi][ni][1]);
            float2 v1 = make_float2(acc[mi][ni][2], acc[mi][ni][3]);
            if (JK) {
                float b0 = bias[gcol], b1 = bias[gcol + 1];
                v0.x += b0; v0.y += b1; v1.x += b0; v1.y += b1;
            }
            if (grow0 < M) *(float2*)(C + (size_t)grow0 * NT + gcol) = v0;
            if (grow1 < M) *(float2*)(C + (size_t)grow1 * NT + gcol) = v1;
        }
    }
}

// ---------------- attention ----------------
__global__ __launch_bounds__(256)
void scores_k(const float* __restrict__ h, const float* __restrict__ asrc,
              const float* __restrict__ adst) {
    int warp = (blockIdx.x * blockDim.x + threadIdx.x) >> 5;
    int lane = threadIdx.x & 31;
    if (warp >= NN) return;
    const float* hp = h + (size_t)warp * HC;
    #pragma unroll
    for (int hh = 0; hh < HH; hh++) {
        float v0 = hp[hh * 64 + lane], v1 = hp[hh * 64 + lane + 32];
        float s = v0 * asrc[hh * 64 + lane] + v1 * asrc[hh * 64 + lane + 32];
        float d = v0 * adst[hh * 64 + lane] + v1 * adst[hh * 64 + lane + 32];
        #pragma unroll
        for (int o = 16; o > 0; o >>= 1) {
            s += __shfl_xor_sync(0xFFFFFFFFu, s, o);
            d += __shfl_xor_sync(0xFFFFFFFFu, d, o);
        }
        if (lane == 0) { g_es[warp * HH + hh] = s; g_ed[warp * HH + hh] = d; }
    }
}

__global__ __launch_bounds__(256)
void softmax_k() {
    int wid = threadIdx.x >> 5, lane = threadIdx.x & 31;
    int n = blockIdx.x * 8 + wid;
    if (n >= NN) return;
    int s = g_rowstart[n], en = g_rowstart[n + 1];
    int deg = en - s;
    if (deg == 0) return;
    float4 ed = *(const float4*)&g_ed[n * 4];

    if (deg <= 32) {
        float v0 = -1e30f, v1 = -1e30f, v2 = -1e30f, v3 = -1e30f;
        if (lane < deg) {
            int src = g_csr_src[s + lane];
            float4 es = *(const float4*)&g_es[src * 4];
            v0 = es.x + ed.x; v0 = fmaxf(v0, 0.2f * v0);
            v1 = es.y + ed.y; v1 = fmaxf(v1, 0.2f * v1);
            v2 = es.z + ed.z; v2 = fmaxf(v2, 0.2f * v2);
            v3 = es.w + ed.w; v3 = fmaxf(v3, 0.2f * v3);
        }
        float m0 = v0, m1 = v1, m2 = v2, m3 = v3;
        #pragma unroll
        for (int o = 16; o > 0; o >>= 1) {
            m0 = fmaxf(m0, __shfl_xor_sync(0xFFFFFFFFu, m0, o));
            m1 = fmaxf(m1, __shfl_xor_sync(0xFFFFFFFFu, m1, o));
            m2 = fmaxf(m2, __shfl_xor_sync(0xFFFFFFFFu, m2, o));
            m3 = fmaxf(m3, __shfl_xor_sync(0xFFFFFFFFu, m3, o));
        }
        float p0 = 0.f, p1 = 0.f, p2 = 0.f, p3 = 0.f;
        if (lane < deg) {
            p0 = expf(v0 - m0); p1 = expf(v1 - m1);
            p2 = expf(v2 - m2); p3 = expf(v3 - m3);
        }
        float d0 = p0, d1 = p1, d2 = p2, d3 = p3;
        #pragma unroll
        for (int o = 16; o > 0; o >>= 1) {
            d0 += __shfl_xor_sync(0xFFFFFFFFu, d0, o);
            d1 += __shfl_xor_sync(0xFFFFFFFFu, d1, o);
            d2 += __shfl_xor_sync(0xFFFFFFFFu, d2, o);
            d3 += __shfl_xor_sync(0xFFFFFFFFu, d3, o);
        }
        if (lane < deg) {
            float4 a;
            a.x = p0 / (d0 + 1e-16f); a.y = p1 / (d1 + 1e-16f);
            a.z = p2 / (d2 + 1e-16f); a.w = p3 / (d3 + 1e-16f);
            *(float4*)&g_alpha[(size_t)(s + lane) * 4] = a;
        }
    } else {
        float m0 = -1e30f, m1 = -1e30f, m2 = -1e30f, m3 = -1e30f;
        for (int p = s + lane; p < en; p += 32) {
            int src = g_csr_src[p];
            float4 es = *(const float4*)&g_es[src * 4];
            float v0 = es.x + ed.x; v0 = fmaxf(v0, 0.2f * v0);
            float v1 = es.y + ed.y; v1 = fmaxf(v1, 0.2f * v1);
            float v2 = es.z + ed.z; v2 = fmaxf(v2, 0.2f * v2);
            float v3 = es.w + ed.w; v3 = fmaxf(v3, 0.2f * v3);
            m0 = fmaxf(m0, v0); m1 = fmaxf(m1, v1);
            m2 = fmaxf(m2, v2); m3 = fmaxf(m3, v3);
        }
        #pragma unroll
        for (int o = 16; o > 0; o >>= 1) {
            m0 = fmaxf(m0, __shfl_xor_sync(0xFFFFFFFFu, m0, o));
            m1 = fmaxf(m1, __shfl_xor_sync(0xFFFFFFFFu, m1, o));
            m2 = fmaxf(m2, __shfl_xor_sync(0xFFFFFFFFu, m2, o));
            m3 = fmaxf(m3, __shfl_xor_sync(0xFFFFFFFFu, m3, o));
        }
        float d0 = 0.f, d1 = 0.f, d2 = 0.f, d3 = 0.f;
        for (int p = s + lane; p < en; p += 32) {
            int src = g_csr_src[p];
            float4 es = *(const float4*)&g_es[src * 4];
            float v0 = es.x + ed.x; v0 = fmaxf(v0, 0.2f * v0);
            float v1 = es.y + ed.y; v1 = fmaxf(v1, 0.2f * v1);
            float v2 = es.z + ed.z; v2 = fmaxf(v2, 0.2f * v2);
            float v3 = es.w + ed.w; v3 = fmaxf(v3, 0.2f * v3);
            float4 a;
            a.x = expf(v0 - m0); a.y = expf(v1 - m1);
            a.z = expf(v2 - m2); a.w = expf(v3 - m3);
            d0 += a.x; d1 += a.y; d2 += a.z; d3 += a.w;
            *(float4*)&g_alpha[(size_t)p * 4] = a;
        }
        #pragma unroll
        for (int o = 16; o > 0; o >>= 1) {
            d0 += __shfl_xor_sync(0xFFFFFFFFu, d0, o);
            d1 += __shfl_xor_sync(0xFFFFFFFFu, d1, o);
            d2 += __shfl_xor_sync(0xFFFFFFFFu, d2, o);
            d3 += __shfl_xor_sync(0xFFFFFFFFu, d3, o);
        }
        float i0 = 1.f / (d0 + 1e-16f), i1 = 1.f / (d1 + 1e-16f);
        float i2 = 1.f / (d2 + 1e-16f), i3 = 1.f / (d3 + 1e-16f);
        for (int p = s + lane; p < en; p += 32) {
            float4 a = *(const float4*)&g_alpha[(size_t)p * 4];
            a.x *= i0; a.y *= i1; a.z *= i2; a.w *= i3;
            *(float4*)&g_alpha[(size_t)p * 4] = a;
        }
    }
}

// 4 nodes/block, 64 threads/node, float4 channels, 4-deep MLP
__global__ __launch_bounds__(256)
void aggregate_k(const float* __restrict__ hfeat, const float* __restrict__ bias,
                 float* __restrict__ out) {
    int grp = threadIdx.x >> 6;
    int t = threadIdx.x & 63;         // channel group: cols 4t..4t+3
    int n = blockIdx.x * 4 + grp;
    if (n >= NN) return;
    int hh = t >> 4;                  // head
    int s = g_rowstart[n], en = g_rowstart[n + 1];
    float4 a0 = {0, 0, 0, 0}, a1 = {0, 0, 0, 0}, a2 = {0, 0, 0, 0}, a3 = {0, 0, 0, 0};
    int p = s;
    for (; p + 4 <= en; p += 4) {
        int s0 = g_csr_src[p], s1 = g_csr_src[p + 1];
        int s2 = g_csr_src[p + 2], s3 = g_csr_src[p + 3];
        float w0 = g_alpha[(size_t)p * 4 + hh];
        float w1 = g_alpha[(size_t)(p + 1) * 4 + hh];
        float w2 = g_alpha[(size_t)(p + 2) * 4 + hh];
        float w3 = g_alpha[(size_t)(p + 3) * 4 + hh];
        float4 f0 = *(const float4*)(hfeat + (size_t)s0 * HC + t * 4);
        float4 f1 = *(const float4*)(hfeat + (size_t)s1 * HC + t * 4);
        float4 f2 = *(const float4*)(hfeat + (size_t)s2 * HC + t * 4);
        float4 f3 = *(const float4*)(hfeat + (size_t)s3 * HC + t * 4);
        a0.x = fmaf(w0, f0.x, a0.x); a0.y = fmaf(w0, f0.y, a0.y);
        a0.z = fmaf(w0, f0.z, a0.z); a0.w = fmaf(w0, f0.w, a0.w);
        a1.x = fmaf(w1, f1.x, a1.x); a1.y = fmaf(w1, f1.y, a1.y);
        a1.z = fmaf(w1, f1.z, a1.z); a1.w = fmaf(w1, f1.w, a1.w);
        a2.x = fmaf(w2, f2.x, a2.x); a2.y = fmaf(w2, f2.y, a2.y);
        a2.z = fmaf(w2, f2.z, a2.z); a2.w = fmaf(w2, f2.w, a2.w);
        a3.x = fmaf(w3, f3.x, a3.x); a3.y = fmaf(w3, f3.y, a3.y);
        a3.z = fmaf(w3, f3.z, a3.z); a3.w = fmaf(w3, f3.w, a3.w);
    }
    for (; p < en; p++) {
        int s0 = g_csr_src[p];
        float w0 = g_alpha[(size_t)p * 4 + hh];
        float4 f0 = *(const float4*)(hfeat + (size_t)s0 * HC + t * 4);
        a0.x = fmaf(w0, f0.x, a0.x); a0.y = fmaf(w0, f0.y, a0.y);
        a0.z = fmaf(w0, f0.z, a0.z); a0.w = fmaf(w0, f0.w, a0.w);
    }
    float4 b = *(const float4*)(bias + t * 4);
    float4 o;
    o.x = (a0.x + a1.x) + (a2.x + a3.x) + b.x;
    o.y = (a0.y + a1.y) + (a2.y + a3.y) + b.y;
    o.z = (a0.z + a1.z) + (a2.z + a3.z) + b.z;
    o.w = (a0.w + a1.w) + (a2.w + a3.w) + b.w;
    *(float4*)(out + (size_t)n * HC + t * 4) = o;
}

// ---------------- BatchNorm ----------------
__global__ __launch_bounds__(256)
void bn_partial_k(const float* __restrict__ x) {
    int ch = threadIdx.x;
    int b = blockIdx.x;
    int r0 = b * ROWS_PER_BLK;
    int r1 = min(r0 + ROWS_PER_BLK, NN);
    float s = 0.f, cs = 0.f, q = 0.f, cq = 0.f;
    for (int r = r0; r < r1; r++) {
        float v = x[(size_t)r * HC + ch];
        float y = v - cs; float t = s + y; cs = (t - s) - y; s = t;
        float v2 = v * v;
        float y2 = v2 - cq; float t2 = q + y2; cq = (t2 - q) - y2; q = t2;
    }
    g_bnpart[b * 512 + ch] = s;
    g_bnpart[b * 512 + 256 + ch] = q;
}
__global__ void bn_final_k(const float* __restrict__ gamma, const float* __restrict__ beta) {
    int ch = threadIdx.x;
    float s = 0.f, cs = 0.f, q = 0.f, cq = 0.f;
    for (int b = 0; b < NBLK; b++) {
        float v = g_bnpart[b * 512 + ch];
        float y = v - cs; float t = s + y; cs = (t - s) - y; s = t;
        float v2 = g_bnpart[b * 512 + 256 + ch];
        float y2 = v2 - cq; float t2 = q + y2; cq = (t2 - q) - y2; q = t2;
    }
    float mean = s / (float)NN;
    float var = q / (float)NN - mean * mean;
    float sc = gamma[ch] * rsqrtf(var + 1e-5f);
    g_bnscale[ch] = sc;
    g_bnshift[ch] = beta[ch] - mean * sc;
}
__global__ void bn_apply_k(const float* __restrict__ x, float* __restrict__ y) {
    int i = blockIdx.x * blockDim.x + threadIdx.x;   // float4 index
    if (i >= NN * HC / 4) return;
    int ch = (i & 63) * 4;
    float4 v = *(const float4*)(x + (size_t)i * 4);
    float4 sc = *(const float4*)&g_bnscale[ch];
    float4 sh = *(const float4*)&g_bnshift[ch];
    v.x = v.x * sc.x + sh.x; v.y = v.y * sc.y + sh.y;
    v.z = v.z * sc.z + sh.z; v.w = v.w * sc.w + sh.w;
    v.x = (v.x > 0.f) ? v.x : expm1f(v.x);
    v.y = (v.y > 0.f) ? v.y : expm1f(v.y);
    v.z = (v.z > 0.f) ? v.z : expm1f(v.z);
    v.w = (v.w > 0.f) ? v.w : expm1f(v.w);
    *(float4*)(y + (size_t)i * 4) = v;
}

// ---------------- host ----------------
#define GDM ((NN + 127) / 128)
#define SMEM_BIG (40960 + 2 * 256 * 160)   // 122880
#define SMEM_SML (40960 + 2 * 64 * 160)    // 61440

extern "C" void kernel_launch(void* const* d_in, const int* in_sizes, int n_in,
                              void* d_out, int out_size) {
    const float* x   = (const float*)d_in[0];
    const void*  eidx = d_in[1];
    const float* W1  = (const float*)d_in[2];
    const float* a1s = (const float*)d_in[3];
    const float* a1d = (const float*)d_in[4];
    const float* b1  = (const float*)d_in[5];
    const float* g1  = (const float*)d_in[6];
    const float* be1 = (const float*)d_in[7];
    const float* W2  = (const float*)d_in[8];
    const float* a2s = (const float*)d_in[9];
    const float* a2d = (const float*)d_in[10];
    const float* b2  = (const float*)d_in[11];
    const float* lW  = (const float*)d_in[12];
    const float* lb  = (const float*)d_in[13];
    float* out = (float*)d_out;

    float *ph, *pgat, *pl1, *pl2;
    cudaGetSymbolAddress((void**)&ph,   g_h);
    cudaGetSymbolAddress((void**)&pgat, g_gat);
    cudaGetSymbolAddress((void**)&pl1,  g_l1);
    cudaGetSymbolAddress((void**)&pl2,  g_l2);
    __nv_bfloat16 *w1h, *w1l, *w2h, *w2l, *w3h, *w3l;
    cudaGetSymbolAddress((void**)&w1h, g_w1t_hi);
    cudaGetSymbolAddress((void**)&w1l, g_w1t_lo);
    cudaGetSymbolAddress((void**)&w2h, g_w2t_hi);
    cudaGetSymbolAddress((void**)&w2l, g_w2t_lo);
    cudaGetSymbolAddress((void**)&w3h, g_w3t_hi);
    cudaGetSymbolAddress((void**)&w3l, g_w3t_lo);
    int* pdeg;
    cudaGetSymbolAddress((void**)&pdeg, g_deg);

    cudaFuncSetAttribute((const void*)mma_gemm_k<FIN, HC, 256, 4, 0>,
                         cudaFuncAttributeMaxDynamicSharedMemorySize, SMEM_BIG);
    cudaFuncSetAttribute((const void*)mma_gemm_k<HC, HC, 256, 4, 0>,
                         cudaFuncAttributeMaxDynamicSharedMemorySize, SMEM_BIG);
    cudaFuncSetAttribute((const void*)mma_gemm_k<HC, OUTC, 64, 2, 1>,
                         cudaFuncAttributeMaxDynamicSharedMemorySize, SMEM_SML);

    // slots: memset=0 detect=1 cvt=2 wconv=3 scan1=4 gemm1=5 (ncu -s 5 -c 1)
    cudaMemsetAsync(pdeg, 0, NN * sizeof(int));
    detect_k<<<1, 32>>>((const unsigned*)eidx);
    cvt_count_k<<<(EE + 255) / 256, 256>>>(eidx);
    wconv_all_k<<<(FIN * HC + HC * HC + HC * OUTC + 255) / 256, 256>>>(W1, W2, lW);
    scan1_k<<<SCB, 256>>>();
    {
        dim3 g(1, GDM);
        mma_gemm_k<FIN, HC, 256, 4, 0><<<g, 512, SMEM_BIG>>>(x, nullptr, w1h, w1l,
                                                             nullptr, ph, NN);
    }
    scan2_k<<<1, 256>>>();
    scan3_k<<<SCB, 256>>>();
    fill_k<<<(EE + 255) / 256, 256>>>();

    scores_k<<<(NN * 32 + 255) / 256, 256>>>(ph, a1s, a1d);
    softmax_k<<<(NN + 7) / 8, 256>>>();
    aggregate_k<<<(NN + 3) / 4, 256>>>(ph, b1, pgat);

    bn_partial_k<<<NBLK, 256>>>(pgat);
    bn_final_k<<<1, 256>>>(g1, be1);
    bn_apply_k<<<(NN * HC / 4 + 255) / 256, 256>>>(pgat, pl1);

    {
        dim3 g(1, GDM);
        mma_gemm_k<HC, HC, 256, 4, 0><<<g, 512, SMEM_BIG>>>(pl1, nullptr, w2h, w2l,
                                                            nullptr, ph, NN);
    }
    scores_k<<<(NN * 32 + 255) / 256, 256>>>(ph, a2s, a2d);
    softmax_k<<<(NN + 7) / 8, 256>>>();
    aggregate_k<<<(NN + 3) / 4, 256>>>(ph, b2, pl2);

    {
        dim3 g(1, GDM);
        mma_gemm_k<HC, OUTC, 64, 2, 1><<<g, 256, SMEM_SML>>>(pl1, pl2, w3h, w3l,
                                                             lb, out, NN);
    }
}

// round 6
// speedup vs baseline: 2.1357x; 1.0892x over previous
#include <cuda_runtime.h>
#include <cuda_bf16.h>
#include <math.h>

#define NN 40000
#define EE 320000
#define FIN 128
#define HH 4
#define HC 256
#define OUTC 64
#define NBLK 160
#define ROWS_PER_BLK 250
#define SCB ((NN + 255) / 256)   // 157

// ---------------- scratch ----------------
__device__ int g_is64;
// zeroed-per-launch region: [0,NN)=deg, [NN,NN+SCB)=scan partial, [NN+SCB,NN+2SCB)=scan prefix
__device__ int g_pre[NN + 2 * SCB];
__device__ __align__(16) int g_src[EE];
__device__ __align__(16) int g_dst[EE];
__device__ int g_rowstart[NN + 1];
__device__ int g_cursor[NN];
__device__ __align__(16) int g_csr_src[EE];
__device__ __align__(16) float g_h[(size_t)NN * HC];
__device__ __align__(16) float g_gat[(size_t)NN * HC];
__device__ __align__(16) float g_l1[(size_t)NN * HC];
__device__ __align__(16) float g_l2[(size_t)NN * HC];
__device__ __align__(16) float g_es[NN * HH];
__device__ __align__(16) float g_ed[NN * HH];
__device__ __align__(16) float g_alpha[(size_t)EE * HH];
__device__ float g_bnpart[NBLK * HC * 2];
__device__ __align__(16) __nv_bfloat16 g_w1t_hi[HC * FIN];
__device__ __align__(16) __nv_bfloat16 g_w1t_lo[HC * FIN];
__device__ __align__(16) __nv_bfloat16 g_w2t_hi[HC * HC];
__device__ __align__(16) __nv_bfloat16 g_w2t_lo[HC * HC];
__device__ __align__(16) __nv_bfloat16 g_w3t_hi[OUTC * HC];
__device__ __align__(16) __nv_bfloat16 g_w3t_lo[OUTC * HC];

// ---------------- helpers ----------------
__device__ __forceinline__ unsigned smem_u32(const void* p) {
    unsigned r;
    asm("{ .reg .u64 t; cvta.to.shared.u64 t, %1; cvt.u32.u64 %0, t; }" : "=r"(r) : "l"(p));
    return r;
}
__device__ __forceinline__ unsigned pack2(float a, float b) {
    __nv_bfloat162 t = __floats2bfloat162_rn(a, b);
    return *reinterpret_cast<unsigned*>(&t);
}
__device__ __forceinline__ void ldsm4(unsigned* d, unsigned a) {
    asm volatile("ldmatrix.sync.aligned.m8n8.x4.shared.b16 {%0,%1,%2,%3}, [%4];"
                 : "=r"(d[0]), "=r"(d[1]), "=r"(d[2]), "=r"(d[3]) : "r"(a));
}
__device__ __forceinline__ void mma16816(float* c, const unsigned* a, const unsigned* b) {
    asm volatile(
        "mma.sync.aligned.m16n8k16.row.col.f32.bf16.bf16.f32 "
        "{%0,%1,%2,%3}, {%4,%5,%6,%7}, {%8,%9}, {%0,%1,%2,%3};"
        : "+f"(c[0]), "+f"(c[1]), "+f"(c[2]), "+f"(c[3])
        : "r"(a[0]), "r"(a[1]), "r"(a[2]), "r"(a[3]), "r"(b[0]), "r"(b[1]));
}
__device__ __forceinline__ void cp16(unsigned saddr, const void* gptr) {
    asm volatile("cp.async.cg.shared.global [%0], [%1], 16;" :: "r"(saddr), "l"(gptr));
}

// ---------------- preprocessing ----------------
__global__ void detect_k(const unsigned* __restrict__ buf) {
    if (threadIdx.x == 0) {
        int any = 0;
        for (int i = 0; i < 64; i++) any |= (buf[2 * i + 1] != 0u);
        g_is64 = any ? 0 : 1;
    }
}
__global__ void cvt_count_k(const void* __restrict__ idx) {
    int e = blockIdx.x * blockDim.x + threadIdx.x;
    if (e >= EE) return;
    int s, d;
    if (g_is64) {
        s = (int)((const long long*)idx)[e];
        d = (int)((const long long*)idx)[(long long)EE + e];
    } else {
        s = ((const int*)idx)[e];
        d = ((const int*)idx)[EE + e];
    }
    g_src[e] = s;
    g_dst[e] = d;
    atomicAdd(&g_pre[d], 1);
}
// single-kernel exclusive scan: decoupled lookback (deterministic)
__global__ void scanfused_k() {
    int t = threadIdx.x, b = blockIdx.x;
    int i = b * 256 + t;
    int v = (i < NN) ? g_pre[i] : 0;
    int lane = t & 31, w = t >> 5;
    int x = v;
    #pragma unroll
    for (int d = 1; d < 32; d <<= 1) {
        int y = __shfl_up_sync(0xFFFFFFFFu, x, d);
        if (lane >= d) x += y;
    }
    __shared__ int ws[8];
    __shared__ int s_off;
    if (lane == 31) ws[w] = x;
    __syncthreads();
    if (t == 0) {
        int s = 0;
        #pragma unroll
        for (int j = 0; j < 8; j++) { s += ws[j]; ws[j] = s; }
        int total = s;
        int* part = g_pre + NN;
        int* pref = g_pre + NN + SCB;
        atomicExch(&part[b], total + 1);
        int run = 0;
        for (int j = b - 1; j >= 0;) {
            int pf = atomicAdd(&pref[j], 0);
            if (pf) { run += pf - 1; break; }
            int pt = atomicAdd(&part[j], 0);
            if (pt) { run += pt - 1; j--; }
        }
        atomicExch(&pref[b], run + total + 1);
        s_off = run;
    }
    __syncthreads();
    int incl = x + (w ? ws[w - 1] : 0);
    int off = s_off;
    if (i < NN) {
        int ex = off + incl - v;
        g_rowstart[i] = ex;
        g_cursor[i] = ex;
    }
    if (i == 0) g_rowstart[NN] = EE;
}
__global__ void fill_k() {
    int e = blockIdx.x * blockDim.x + threadIdx.x;
    if (e >= EE) return;
    int pos = atomicAdd(&g_cursor[g_dst[e]], 1);
    g_csr_src[pos] = g_src[e];
}

// ---------------- merged weight transpose + bf16 split ----------------
__global__ void wconv_all_k(const float* __restrict__ W1, const float* __restrict__ W2,
                            const float* __restrict__ W3) {
    int gid = blockIdx.x * blockDim.x + threadIdx.x;
    const float* W;
    __nv_bfloat16 *Thi, *Tlo;
    int K, N, idx;
    if (gid < FIN * HC) {
        W = W1; Thi = g_w1t_hi; Tlo = g_w1t_lo; K = FIN; N = HC; idx = gid;
    } else if (gid < FIN * HC + HC * HC) {
        W = W2; Thi = g_w2t_hi; Tlo = g_w2t_lo; K = HC; N = HC; idx = gid - FIN * HC;
    } else if (gid < FIN * HC + HC * HC + HC * OUTC) {
        W = W3; Thi = g_w3t_hi; Tlo = g_w3t_lo; K = HC; N = OUTC;
        idx = gid - FIN * HC - HC * HC;
    } else return;
    int k = idx / N, n = idx % N;
    float v = W[idx];
    __nv_bfloat16 h = __float2bfloat16_rn(v);
    float r = v - __bfloat162float(h);
    Thi[(size_t)n * K + k] = h;
    Tlo[(size_t)n * K + k] = __float2bfloat16_rn(r);
}

// ---------------- pipelined mma.sync split-bf16 GEMM (+ fused attention scores) ----------------
// SCORES==1 requires NTILE/WARPS_N == 64 and NTILE == NT (full row per block):
// warp wc's 64-col slab == head wc; epilogue computes es/ed = <h, a_src/a_dst>.
template <int KT, int NT, int NTILE, int WARPS_N, int JK, int SCORES>
__global__ __launch_bounds__(128 * WARPS_N)
void mma_gemm_k(const float* __restrict__ A, const float* __restrict__ A2,
                const __nv_bfloat16* __restrict__ Bhi, const __nv_bfloat16* __restrict__ Blo,
                const float* __restrict__ bias, float* __restrict__ C,
                const float* __restrict__ asrc, const float* __restrict__ adst, int M) {
    constexpr int THREADS = 128 * WARPS_N;
    constexpr int WN = NTILE / WARPS_N;
    constexpr int NI = WN / 8;
    constexpr int LDA = 1024 / THREADS;
    constexpr int LDB = 8 * NTILE / THREADS;
    constexpr int CH = KT / 32;
    constexpr unsigned ABUF = 20480;
    constexpr unsigned BOFF = 2 * ABUF;
    constexpr unsigned BBUF = NTILE * 160;

    extern __shared__ char dynsm[];
    unsigned sbase = smem_u32(dynsm);
    int tid = threadIdx.x, lane = tid & 31, wid = tid >> 5;
    int wr = wid & 3, wc = wid >> 2;
    int rowBase = blockIdx.y * 128;
    int colBase = blockIdx.x * NTILE;
    float acc[2][NI][4] = {};
    float4 av[LDA], av2[LDA];

    auto loadA = [&](int c) {
        #pragma unroll
        for (int i = 0; i < LDA; i++) {
            int q = tid + i * THREADS;
            int r = q >> 3, cc = (q & 7) * 4;
            int grow = rowBase + r;
            av[i] = make_float4(0.f, 0.f, 0.f, 0.f);
            av2[i] = make_float4(0.f, 0.f, 0.f, 0.f);
            if (grow < M) {
                av[i] = *(const float4*)(A + (size_t)grow * KT + c * 32 + cc);
                if (JK) av2[i] = *(const float4*)(A2 + (size_t)grow * KT + c * 32 + cc);
            }
        }
    };
    auto storeA = [&](int buf) {
        #pragma unroll
        for (int i = 0; i < LDA; i++) {
            int q = tid + i * THREADS;
            int r = q >> 3, cc = (q & 7) * 4;
            float4 v = av[i];
            if (JK) {
                float4 w = av2[i];
                v.x = fmaxf(v.x, w.x); v.y = fmaxf(v.y, w.y);
                v.z = fmaxf(v.z, w.z); v.w = fmaxf(v.w, w.w);
            }
            float hx = __bfloat162float(__float2bfloat16_rn(v.x));
            float hy = __bfloat162float(__float2bfloat16_rn(v.y));
            float hz = __bfloat162float(__float2bfloat16_rn(v.z));
            float hw = __bfloat162float(__float2bfloat16_rn(v.w));
            unsigned off = buf * ABUF + (unsigned)(r * 40 + cc) * 2;
            *(uint2*)(dynsm + off) = make_uint2(pack2(hx, hy), pack2(hz, hw));
            *(uint2*)(dynsm + off + 10240) =
                make_uint2(pack2(v.x - hx, v.y - hy), pack2(v.z - hz, v.w - hw));
        }
    };
    auto loadB = [&](int c, int buf) {
        #pragma unroll
        for (int i = 0; i < LDB; i++) {
            int q = tid + i * THREADS;
            int hl = q / (4 * NTILE);
            int rem = q - hl * 4 * NTILE;
            int r = rem >> 2, seg = rem & 3;
            const __nv_bfloat16* src = hl ? Blo : Bhi;
            unsigned soff = BOFF + buf * BBUF + hl * (NTILE * 80) +
                            (unsigned)(r * 40 + seg * 8) * 2;
            cp16(sbase + soff, src + (size_t)(colBase + r) * KT + c * 32 + seg * 8);
        }
        asm volatile("cp.async.commit_group;");
    };
    auto compute = [&](int buf) {
        unsigned saA = sbase + buf * ABUF;
        unsigned saB = sbase + BOFF + buf * BBUF;
        #pragma unroll
        for (int kk = 0; kk < 32; kk += 16) {
            unsigned ah[2][4], al[2][4], bh[NI / 2][4], bl[NI / 2][4];
            #pragma unroll
            for (int mi = 0; mi < 2; mi++) {
                int row = wr * 32 + mi * 16 + (lane & 7) + ((lane & 8) ? 8 : 0);
                int col = kk + ((lane & 16) ? 8 : 0);
                ldsm4(ah[mi], saA + (unsigned)(row * 40 + col) * 2);
                ldsm4(al[mi], saA + 10240 + (unsigned)(row * 40 + col) * 2);
            }
            #pragma unroll
            for (int nb = 0; nb < NI / 2; nb++) {
                int row = wc * WN + nb * 16 + ((lane & 16) ? 8 : 0) + (lane & 7);
                int col = kk + ((lane & 8) ? 8 : 0);
                ldsm4(bh[nb], saB + (unsigned)(row * 40 + col) * 2);
                ldsm4(bl[nb], saB + (unsigned)(NTILE * 80) + (unsigned)(row * 40 + col) * 2);
            }
            #pragma unroll
            for (int mi = 0; mi < 2; mi++)
                #pragma unroll
                for (int nb = 0; nb < NI / 2; nb++) {
                    mma16816(acc[mi][2 * nb], ah[mi], &bh[nb][0]);
                    mma16816(acc[mi][2 * nb], ah[mi], &bl[nb][0]);
                    mma16816(acc[mi][2 * nb], al[mi], &bh[nb][0]);
                    mma16816(acc[mi][2 * nb + 1], ah[mi], &bh[nb][2]);
                    mma16816(acc[mi][2 * nb + 1], ah[mi], &bl[nb][2]);
                    mma16816(acc[mi][2 * nb + 1], al[mi], &bh[nb][2]);
                }
        }
    };

    loadB(0, 0);
    loadA(0);
    storeA(0);
    asm volatile("cp.async.wait_group 0;");
    __syncthreads();
    for (int c = 0; c < CH; c++) {
        int buf = c & 1;
        if (c + 1 < CH) { loadB(c + 1, buf ^ 1); loadA(c + 1); }
        compute(buf);
        if (c + 1 < CH) {
            storeA(buf ^ 1);
            asm volatile("cp.async.wait_group 0;");
        }
        __syncthreads();
    }
    // epilogue: C store
    #pragma unroll
    for (int mi = 0; mi < 2; mi++) {
        int grow0 = rowBase + wr * 32 + mi * 16 + (lane >> 2);
        int grow1 = grow0 + 8;
        #pragma unroll
        for (int ni = 0; ni < NI; ni++) {
            int gcol = colBase + wc * WN + ni * 8 + (lane & 3) * 2;
            float2 v0 = make_float2(acc[mi][ni][0], acc[mi][ni][1]);
            float2 v1 = make_float2(acc[mi][ni][2], acc[mi][ni][3]);
            if (JK) {
                float b0 = bias[gcol], b1 = bias[gcol + 1];
                v0.x += b0; v0.y += b1; v1.x += b0; v1.y += b1;
            }
            if (grow0 < M) *(float2*)(C + (size_t)grow0 * NT + gcol) = v0;
            if (grow1 < M) *(float2*)(C + (size_t)grow1 * NT + gcol) = v1;
        }
    }
    // fused attention scores: head = wc
    if (SCORES) {
        float as[NI][2], ad[NI][2];
        #pragma unroll
        for (int ni = 0; ni < NI; ni++) {
            int c = wc * WN + ni * 8 + (lane & 3) * 2;
            as[ni][0] = asrc[c]; as[ni][1] = asrc[c + 1];
            ad[ni][0] = adst[c]; ad[ni][1] = adst[c + 1];
        }
        #pragma unroll
        for (int mi = 0; mi < 2; mi++) {
            float e0 = 0.f, e1 = 0.f, d0 = 0.f, d1 = 0.f;
            #pragma unroll
            for (int ni = 0; ni < NI; ni++) {
                e0 = fmaf(acc[mi][ni][0], as[ni][0], e0);
                e0 = fmaf(acc[mi][ni][1], as[ni][1], e0);
                e1 = fmaf(acc[mi][ni][2], as[ni][0], e1);
                e1 = fmaf(acc[mi][ni][3], as[ni][1], e1);
                d0 = fmaf(acc[mi][ni][0], ad[ni][0], d0);
                d0 = fmaf(acc[mi][ni][1], ad[ni][1], d0);
                d1 = fmaf(acc[mi][ni][2], ad[ni][0], d1);
                d1 = fmaf(acc[mi][ni][3], ad[ni][1], d1);
            }
            e0 += __shfl_xor_sync(0xFFFFFFFFu, e0, 1); e0 += __shfl_xor_sync(0xFFFFFFFFu, e0, 2);
            e1 += __shfl_xor_sync(0xFFFFFFFFu, e1, 1); e1 += __shfl_xor_sync(0xFFFFFFFFu, e1, 2);
            d0 += __shfl_xor_sync(0xFFFFFFFFu, d0, 1); d0 += __shfl_xor_sync(0xFFFFFFFFu, d0, 2);
            d1 += __shfl_xor_sync(0xFFFFFFFFu, d1, 1); d1 += __shfl_xor_sync(0xFFFFFFFFu, d1, 2);
            if ((lane & 3) == 0) {
                int r0 = rowBase + wr * 32 + mi * 16 + (lane >> 2);
                int r1 = r0 + 8;
                if (r0 < M) { g_es[r0 * 4 + wc] = e0; g_ed[r0 * 4 + wc] = d0; }
                if (r1 < M) { g_es[r1 * 4 + wc] = e1; g_ed[r1 * 4 + wc] = d1; }
            }
        }
    }
}

// ---------------- fused softmax + aggregate: one warp per node ----------------
__global__ __launch_bounds__(256)
void softagg_k(const float* __restrict__ hfeat, const float* __restrict__ bias,
               float* __restrict__ out) {
    __shared__ float sal[8][32][4];   // 4 KB: [warp][edge][head]
    int t = threadIdx.x, wid = t >> 5, lane = t & 31;
    int n = blockIdx.x * 8 + wid;
    if (n >= NN) return;
    int s = g_rowstart[n], en = g_rowstart[n + 1];
    int deg = en - s;
    bool small = (deg <= 32);

    // ---- phase 1: softmax (warp-local) ----
    if (deg > 0) {
        float4 ed = *(const float4*)&g_ed[n * 4];
        if (small) {
            float v0 = -1e30f, v1 = -1e30f, v2 = -1e30f, v3 = -1e30f;
            if (lane < deg) {
                int src = g_csr_src[s + lane];
                float4 es = *(const float4*)&g_es[src * 4];
                v0 = es.x + ed.x; v0 = fmaxf(v0, 0.2f * v0);
                v1 = es.y + ed.y; v1 = fmaxf(v1, 0.2f * v1);
                v2 = es.z + ed.z; v2 = fmaxf(v2, 0.2f * v2);
                v3 = es.w + ed.w; v3 = fmaxf(v3, 0.2f * v3);
            }
            float m0 = v0, m1 = v1, m2 = v2, m3 = v3;
            #pragma unroll
            for (int o = 16; o > 0; o >>= 1) {
                m0 = fmaxf(m0, __shfl_xor_sync(0xFFFFFFFFu, m0, o));
                m1 = fmaxf(m1, __shfl_xor_sync(0xFFFFFFFFu, m1, o));
                m2 = fmaxf(m2, __shfl_xor_sync(0xFFFFFFFFu, m2, o));
                m3 = fmaxf(m3, __shfl_xor_sync(0xFFFFFFFFu, m3, o));
            }
            float p0 = 0.f, p1 = 0.f, p2 = 0.f, p3 = 0.f;
            if (lane < deg) {
                p0 = __expf(v0 - m0); p1 = __expf(v1 - m1);
                p2 = __expf(v2 - m2); p3 = __expf(v3 - m3);
            }
            float d0 = p0, d1 = p1, d2 = p2, d3 = p3;
            #pragma unroll
            for (int o = 16; o > 0; o >>= 1) {
                d0 += __shfl_xor_sync(0xFFFFFFFFu, d0, o);
                d1 += __shfl_xor_sync(0xFFFFFFFFu, d1, o);
                d2 += __shfl_xor_sync(0xFFFFFFFFu, d2, o);
                d3 += __shfl_xor_sync(0xFFFFFFFFu, d3, o);
            }
            if (lane < deg) {
                sal[wid][lane][0] = p0 / (d0 + 1e-16f);
                sal[wid][lane][1] = p1 / (d1 + 1e-16f);
                sal[wid][lane][2] = p2 / (d2 + 1e-16f);
                sal[wid][lane][3] = p3 / (d3 + 1e-16f);
            }
        } else {
            float m0 = -1e30f, m1 = -1e30f, m2 = -1e30f, m3 = -1e30f;
            for (int p = s + lane; p < en; p += 32) {
                int src = g_csr_src[p];
                float4 es = *(const float4*)&g_es[src * 4];
                float v0 = es.x + ed.x; v0 = fmaxf(v0, 0.2f * v0);
                float v1 = es.y + ed.y; v1 = fmaxf(v1, 0.2f * v1);
                float v2 = es.z + ed.z; v2 = fmaxf(v2, 0.2f * v2);
                float v3 = es.w + ed.w; v3 = fmaxf(v3, 0.2f * v3);
                m0 = fmaxf(m0, v0); m1 = fmaxf(m1, v1);
                m2 = fmaxf(m2, v2); m3 = fmaxf(m3, v3);
            }
            #pragma unroll
            for (int o = 16; o > 0; o >>= 1) {
                m0 = fmaxf(m0, __shfl_xor_sync(0xFFFFFFFFu, m0, o));
                m1 = fmaxf(m1, __shfl_xor_sync(0xFFFFFFFFu, m1, o));
                m2 = fmaxf(m2, __shfl_xor_sync(0xFFFFFFFFu, m2, o));
                m3 = fmaxf(m3, __shfl_xor_sync(0xFFFFFFFFu, m3, o));
            }
            float d0 = 0.f, d1 = 0.f, d2 = 0.f, d3 = 0.f;
            for (int p = s + lane; p < en; p += 32) {
                int src = g_csr_src[p];
                float4 es = *(const float4*)&g_es[src * 4];
                float v0 = es.x + ed.x; v0 = fmaxf(v0, 0.2f * v0);
                float v1 = es.y + ed.y; v1 = fmaxf(v1, 0.2f * v1);
                float v2 = es.z + ed.z; v2 = fmaxf(v2, 0.2f * v2);
                float v3 = es.w + ed.w; v3 = fmaxf(v3, 0.2f * v3);
                float4 a;
                a.x = __expf(v0 - m0); a.y = __expf(v1 - m1);
                a.z = __expf(v2 - m2); a.w = __expf(v3 - m3);
                d0 += a.x; d1 += a.y; d2 += a.z; d3 += a.w;
                *(float4*)&g_alpha[(size_t)p * 4] = a;
            }
            #pragma unroll
            for (int o = 16; o > 0; o >>= 1) {
                d0 += __shfl_xor_sync(0xFFFFFFFFu, d0, o);
                d1 += __shfl_xor_sync(0xFFFFFFFFu, d1, o);
                d2 += __shfl_xor_sync(0xFFFFFFFFu, d2, o);
                d3 += __shfl_xor_sync(0xFFFFFFFFu, d3, o);
            }
            float i0 = 1.f / (d0 + 1e-16f), i1 = 1.f / (d1 + 1e-16f);
            float i2 = 1.f / (d2 + 1e-16f), i3 = 1.f / (d3 + 1e-16f);
            for (int p = s + lane; p < en; p += 32) {
                float4 a = *(const float4*)&g_alpha[(size_t)p * 4];
                a.x *= i0; a.y *= i1; a.z *= i2; a.w *= i3;
                *(float4*)&g_alpha[(size_t)p * 4] = a;
            }
        }
    }
    __syncwarp();

    // ---- phase 2: aggregate (same warp; 32 threads x 2 float4 per node) ----
    int h0 = lane >> 4;              // head of float4 at ch lane*4
    int h1 = h0 + 2;                 // head of float4 at ch 128+lane*4
    int c0 = lane * 4, c1 = 128 + lane * 4;
    float4 A = {0, 0, 0, 0}, B = {0, 0, 0, 0};
    float4 A2 = {0, 0, 0, 0}, B2 = {0, 0, 0, 0};
    int p = s, j = 0;
    for (; p + 2 <= en; p += 2, j += 2) {
        int s0 = g_csr_src[p], s1 = g_csr_src[p + 1];
        float w00, w01, w10, w11;
        if (small) {
            w00 = sal[wid][j][h0];     w01 = sal[wid][j][h1];
            w10 = sal[wid][j + 1][h0]; w11 = sal[wid][j + 1][h1];
        } else {
            w00 = g_alpha[(size_t)p * 4 + h0];       w01 = g_alpha[(size_t)p * 4 + h1];
            w10 = g_alpha[(size_t)(p + 1) * 4 + h0]; w11 = g_alpha[(size_t)(p + 1) * 4 + h1];
        }
        float4 f0a = *(const float4*)(hfeat + (size_t)s0 * HC + c0);
        float4 f0b = *(const float4*)(hfeat + (size_t)s0 * HC + c1);
        float4 f1a = *(const float4*)(hfeat + (size_t)s1 * HC + c0);
        float4 f1b = *(const float4*)(hfeat + (size_t)s1 * HC + c1);
        A.x = fmaf(w00, f0a.x, A.x); A.y = fmaf(w00, f0a.y, A.y);
        A.z = fmaf(w00, f0a.z, A.z); A.w = fmaf(w00, f0a.w, A.w);
        B.x = fmaf(w01, f0b.x, B.x); B.y = fmaf(w01, f0b.y, B.y);
        B.z = fmaf(w01, f0b.z, B.z); B.w = fmaf(w01, f0b.w, B.w);
        A2.x = fmaf(w10, f1a.x, A2.x); A2.y = fmaf(w10, f1a.y, A2.y);
        A2.z = fmaf(w10, f1a.z, A2.z); A2.w = fmaf(w10, f1a.w, A2.w);
        B2.x = fmaf(w11, f1b.x, B2.x); B2.y = fmaf(w11, f1b.y, B2.y);
        B2.z = fmaf(w11, f1b.z, B2.z); B2.w = fmaf(w11, f1b.w, B2.w);
    }
    if (p < en) {
        int s0 = g_csr_src[p];
        float w00, w01;
        if (small) { w00 = sal[wid][j][h0]; w01 = sal[wid][j][h1]; }
        else { w00 = g_alpha[(size_t)p * 4 + h0]; w01 = g_alpha[(size_t)p * 4 + h1]; }
        float4 f0a = *(const float4*)(hfeat + (size_t)s0 * HC + c0);
        float4 f0b = *(const float4*)(hfeat + (size_t)s0 * HC + c1);
        A.x = fmaf(w00, f0a.x, A.x); A.y = fmaf(w00, f0a.y, A.y);
        A.z = fmaf(w00, f0a.z, A.z); A.w = fmaf(w00, f0a.w, A.w);
        B.x = fmaf(w01, f0b.x, B.x); B.y = fmaf(w01, f0b.y, B.y);
        B.z = fmaf(w01, f0b.z, B.z); B.w = fmaf(w01, f0b.w, B.w);
    }
    float4 ba = *(const float4*)(bias + c0);
    float4 bb = *(const float4*)(bias + c1);
    float4 oa, ob;
    oa.x = A.x + A2.x + ba.x; oa.y = A.y + A2.y + ba.y;
    oa.z = A.z + A2.z + ba.z; oa.w = A.w + A2.w + ba.w;
    ob.x = B.x + B2.x + bb.x; ob.y = B.y + B2.y + bb.y;
    ob.z = B.z + B2.z + bb.z; ob.w = B.w + B2.w + bb.w;
    *(float4*)(out + (size_t)n * HC + c0) = oa;
    *(float4*)(out + (size_t)n * HC + c1) = ob;
}

// ---------------- BatchNorm ----------------
__global__ __launch_bounds__(256)
void bn_partial_k(const float* __restrict__ x) {
    int ch = threadIdx.x;
    int b = blockIdx.x;
    int r0 = b * ROWS_PER_BLK;
    int r1 = min(r0 + ROWS_PER_BLK, NN);
    float s = 0.f, q = 0.f;
    for (int r = r0; r < r1; r++) {
        float v = x[(size_t)r * HC + ch];
        s += v;
        q += v * v;
    }
    g_bnpart[b * 512 + ch] = s;
    g_bnpart[b * 512 + 256 + ch] = q;
}
// fused final-reduce + apply (each block redundantly reduces the 160 partials)
__global__ __launch_bounds__(256)
void bn_apply_k(const float* __restrict__ x, const float* __restrict__ gamma,
                const float* __restrict__ beta, float* __restrict__ y) {
    __shared__ float ssc[HC], ssh[HC];
    int t = threadIdx.x;
    float s = 0.f, q = 0.f;
    for (int b = 0; b < NBLK; b++) {
        s += g_bnpart[b * 512 + t];
        q += g_bnpart[b * 512 + 256 + t];
    }
    float mean = s / (float)NN;
    float var = q / (float)NN - mean * mean;
    float sc = gamma[t] * rsqrtf(var + 1e-5f);
    ssc[t] = sc;
    ssh[t] = beta[t] - mean * sc;
    __syncthreads();
    for (long long i = blockIdx.x * 256 + t; i < (long long)NN * 64; i += (long long)gridDim.x * 256) {
        int ch = ((int)i & 63) * 4;
        float4 v = *(const float4*)(x + i * 4);
        v.x = v.x * ssc[ch] + ssh[ch];
        v.y = v.y * ssc[ch + 1] + ssh[ch + 1];
        v.z = v.z * ssc[ch + 2] + ssh[ch + 2];
        v.w = v.w * ssc[ch + 3] + ssh[ch + 3];
        v.x = (v.x > 0.f) ? v.x : expm1f(v.x);
        v.y = (v.y > 0.f) ? v.y : expm1f(v.y);
        v.z = (v.z > 0.f) ? v.z : expm1f(v.z);
        v.w = (v.w > 0.f) ? v.w : expm1f(v.w);
        *(float4*)(y + i * 4) = v;
    }
}

// ---------------- host ----------------
#define GDM ((NN + 127) / 128)
#define SMEM_BIG (40960 + 2 * 256 * 160)   // 122880
#define SMEM_SML (40960 + 2 * 64 * 160)    // 61440

extern "C" void kernel_launch(void* const* d_in, const int* in_sizes, int n_in,
                              void* d_out, int out_size) {
    const float* x   = (const float*)d_in[0];
    const void*  eidx = d_in[1];
    const float* W1  = (const float*)d_in[2];
    const float* a1s = (const float*)d_in[3];
    const float* a1d = (const float*)d_in[4];
    const float* b1  = (const float*)d_in[5];
    const float* g1  = (const float*)d_in[6];
    const float* be1 = (const float*)d_in[7];
    const float* W2  = (const float*)d_in[8];
    const float* a2s = (const float*)d_in[9];
    const float* a2d = (const float*)d_in[10];
    const float* b2  = (const float*)d_in[11];
    const float* lW  = (const float*)d_in[12];
    const float* lb  = (const float*)d_in[13];
    float* out = (float*)d_out;

    float *ph, *pgat, *pl1, *pl2;
    cudaGetSymbolAddress((void**)&ph,   g_h);
    cudaGetSymbolAddress((void**)&pgat, g_gat);
    cudaGetSymbolAddress((void**)&pl1,  g_l1);
    cudaGetSymbolAddress((void**)&pl2,  g_l2);
    __nv_bfloat16 *w1h, *w1l, *w2h, *w2l, *w3h, *w3l;
    cudaGetSymbolAddress((void**)&w1h, g_w1t_hi);
    cudaGetSymbolAddress((void**)&w1l, g_w1t_lo);
    cudaGetSymbolAddress((void**)&w2h, g_w2t_hi);
    cudaGetSymbolAddress((void**)&w2l, g_w2t_lo);
    cudaGetSymbolAddress((void**)&w3h, g_w3t_hi);
    cudaGetSymbolAddress((void**)&w3l, g_w3t_lo);
    int* ppre;
    cudaGetSymbolAddress((void**)&ppre, g_pre);

    cudaFuncSetAttribute((const void*)mma_gemm_k<FIN, HC, 256, 4, 0, 1>,
                         cudaFuncAttributeMaxDynamicSharedMemorySize, SMEM_BIG);
    cudaFuncSetAttribute((const void*)mma_gemm_k<HC, HC, 256, 4, 0, 1>,
                         cudaFuncAttributeMaxDynamicSharedMemorySize, SMEM_BIG);
    cudaFuncSetAttribute((const void*)mma_gemm_k<HC, OUTC, 64, 2, 1, 0>,
                         cudaFuncAttributeMaxDynamicSharedMemorySize, SMEM_SML);

    // nodes: memset0 detect1 cvt2 wconv3 gemm1@4 (ncu -s 5 -c 1 target)
    cudaMemsetAsync(ppre, 0, (NN + 2 * SCB) * sizeof(int));
    detect_k<<<1, 32>>>((const unsigned*)eidx);
    cvt_count_k<<<(EE + 255) / 256, 256>>>(eidx);
    wconv_all_k<<<(FIN * HC + HC * HC + HC * OUTC + 255) / 256, 256>>>(W1, W2, lW);
    {
        dim3 g(1, GDM);
        mma_gemm_k<FIN, HC, 256, 4, 0, 1><<<g, 512, SMEM_BIG>>>(
            x, nullptr, w1h, w1l, nullptr, ph, a1s, a1d, NN);
    }
    scanfused_k<<<SCB, 256>>>();
    fill_k<<<(EE + 255) / 256, 256>>>();

    softagg_k<<<(NN + 7) / 8, 256>>>(ph, b1, pgat);
    bn_partial_k<<<NBLK, 256>>>(pgat);
    bn_apply_k<<<296, 256>>>(pgat, g1, be1, pl1);

    {
        dim3 g(1, GDM);
        mma_gemm_k<HC, HC, 256, 4, 0, 1><<<g, 512, SMEM_BIG>>>(
            pl1, nullptr, w2h, w2l, nullptr, ph, a2s, a2d, NN);
    }
    softagg_k<<<(NN + 7) / 8, 256>>>(ph, b2, pl2);

    {
        dim3 g(1, GDM);
        mma_gemm_k<HC, OUTC, 64, 2, 1, 0><<<g, 256, SMEM_SML>>>(
            pl1, pl2, w3h, w3l, lb, out, nullptr, nullptr, NN);
    }
}

// round 7
// speedup vs baseline: 2.2630x; 1.0596x over previous
#include <cuda_runtime.h>
#include <cuda_bf16.h>
#include <math.h>

#define NN 40000
#define EE 320000
#define FIN 128
#define HH 4
#define HC 256
#define OUTC 64
#define SCB ((NN + 255) / 256)   // 157

// ---------------- scratch ----------------
__device__ int g_is64;
// zeroed-per-launch: [0,NN)=deg, [NN,NN+SCB)=scan partial, [NN+SCB,NN+2SCB)=scan prefix
__device__ int g_pre[NN + 2 * SCB];
__device__ __align__(16) int g_src[EE];
__device__ __align__(16) int g_dst[EE];
__device__ int g_rowstart[NN + 1];
__device__ int g_cursor[NN];
__device__ __align__(16) int g_csr_src[EE];
__device__ __align__(16) float g_h[(size_t)NN * HC];
__device__ __align__(16) float g_gat[(size_t)NN * HC];
__device__ __align__(16) float g_l1[(size_t)NN * HC];
__device__ __align__(16) float g_l2[(size_t)NN * HC];
__device__ __align__(16) float g_es[NN * HH];
__device__ __align__(16) float g_ed[NN * HH];
__device__ __align__(16) float g_alpha[(size_t)EE * HH];
__device__ float g_bnsum[2 * HC];          // [0,256)=sum, [256,512)=sumsq (atomic-accumulated)
__device__ __align__(16) __nv_bfloat16 g_w1t_hi[HC * FIN];
__device__ __align__(16) __nv_bfloat16 g_w1t_lo[HC * FIN];
__device__ __align__(16) __nv_bfloat16 g_w2t_hi[HC * HC];
__device__ __align__(16) __nv_bfloat16 g_w2t_lo[HC * HC];
__device__ __align__(16) __nv_bfloat16 g_w3t_hi[OUTC * HC];
__device__ __align__(16) __nv_bfloat16 g_w3t_lo[OUTC * HC];

// ---------------- helpers ----------------
__device__ __forceinline__ unsigned smem_u32(const void* p) {
    unsigned r;
    asm("{ .reg .u64 t; cvta.to.shared.u64 t, %1; cvt.u32.u64 %0, t; }" : "=r"(r) : "l"(p));
    return r;
}
__device__ __forceinline__ unsigned pack2(float a, float b) {
    __nv_bfloat162 t = __floats2bfloat162_rn(a, b);
    return *reinterpret_cast<unsigned*>(&t);
}
__device__ __forceinline__ void ldsm4(unsigned* d, unsigned a) {
    asm volatile("ldmatrix.sync.aligned.m8n8.x4.shared.b16 {%0,%1,%2,%3}, [%4];"
                 : "=r"(d[0]), "=r"(d[1]), "=r"(d[2]), "=r"(d[3]) : "r"(a));
}
__device__ __forceinline__ void mma16816(float* c, const unsigned* a, const unsigned* b) {
    asm volatile(
        "mma.sync.aligned.m16n8k16.row.col.f32.bf16.bf16.f32 "
        "{%0,%1,%2,%3}, {%4,%5,%6,%7}, {%8,%9}, {%0,%1,%2,%3};"
        : "+f"(c[0]), "+f"(c[1]), "+f"(c[2]), "+f"(c[3])
        : "r"(a[0]), "r"(a[1]), "r"(a[2]), "r"(a[3]), "r"(b[0]), "r"(b[1]));
}
__device__ __forceinline__ void cp16(unsigned saddr, const void* gptr) {
    asm volatile("cp.async.cg.shared.global [%0], [%1], 16;" :: "r"(saddr), "l"(gptr));
}

// ---------------- preprocessing ----------------
__global__ void detect_k(const unsigned* __restrict__ buf) {
    if (threadIdx.x == 0) {
        int any = 0;
        for (int i = 0; i < 64; i++) any |= (buf[2 * i + 1] != 0u);
        g_is64 = any ? 0 : 1;
    }
}
__global__ void cvt_count_k(const void* __restrict__ idx) {
    int e = blockIdx.x * blockDim.x + threadIdx.x;
    if (e >= EE) return;
    int s, d;
    if (g_is64) {
        s = (int)((const long long*)idx)[e];
        d = (int)((const long long*)idx)[(long long)EE + e];
    } else {
        s = ((const int*)idx)[e];
        d = ((const int*)idx)[EE + e];
    }
    g_src[e] = s;
    g_dst[e] = d;
    atomicAdd(&g_pre[d], 1);
}
// single-kernel exclusive scan with decoupled lookback
__global__ void scanfused_k() {
    int t = threadIdx.x, b = blockIdx.x;
    int i = b * 256 + t;
    int v = (i < NN) ? g_pre[i] : 0;
    int lane = t & 31, w = t >> 5;
    int x = v;
    #pragma unroll
    for (int d = 1; d < 32; d <<= 1) {
        int y = __shfl_up_sync(0xFFFFFFFFu, x, d);
        if (lane >= d) x += y;
    }
    __shared__ int ws[8];
    __shared__ int s_off;
    if (lane == 31) ws[w] = x;
    __syncthreads();
    if (t == 0) {
        int s = 0;
        #pragma unroll
        for (int j = 0; j < 8; j++) { s += ws[j]; ws[j] = s; }
        int total = s;
        int* part = g_pre + NN;
        int* pref = g_pre + NN + SCB;
        atomicExch(&part[b], total + 1);
        int run = 0;
        for (int j = b - 1; j >= 0;) {
            int pf = atomicAdd(&pref[j], 0);
            if (pf) { run += pf - 1; break; }
            int pt = atomicAdd(&part[j], 0);
            if (pt) { run += pt - 1; j--; }
        }
        atomicExch(&pref[b], run + total + 1);
        s_off = run;
    }
    __syncthreads();
    int incl = x + (w ? ws[w - 1] : 0);
    int off = s_off;
    if (i < NN) {
        int ex = off + incl - v;
        g_rowstart[i] = ex;
        g_cursor[i] = ex;
    }
    if (i == 0) g_rowstart[NN] = EE;
}
__global__ void fill_k() {
    int e = blockIdx.x * blockDim.x + threadIdx.x;
    if (e >= EE) return;
    int pos = atomicAdd(&g_cursor[g_dst[e]], 1);
    g_csr_src[pos] = g_src[e];
}

// ---------------- merged weight transpose + bf16 split ----------------
__global__ void wconv_all_k(const float* __restrict__ W1, const float* __restrict__ W2,
                            const float* __restrict__ W3) {
    int gid = blockIdx.x * blockDim.x + threadIdx.x;
    const float* W;
    __nv_bfloat16 *Thi, *Tlo;
    int K, N, idx;
    if (gid < FIN * HC) {
        W = W1; Thi = g_w1t_hi; Tlo = g_w1t_lo; K = FIN; N = HC; idx = gid;
    } else if (gid < FIN * HC + HC * HC) {
        W = W2; Thi = g_w2t_hi; Tlo = g_w2t_lo; K = HC; N = HC; idx = gid - FIN * HC;
    } else if (gid < FIN * HC + HC * HC + HC * OUTC) {
        W = W3; Thi = g_w3t_hi; Tlo = g_w3t_lo; K = HC; N = OUTC;
        idx = gid - FIN * HC - HC * HC;
    } else return;
    int k = idx / N, n = idx % N;
    float v = W[idx];
    __nv_bfloat16 h = __float2bfloat16_rn(v);
    float r = v - __bfloat162float(h);
    Thi[(size_t)n * K + k] = h;
    Tlo[(size_t)n * K + k] = __float2bfloat16_rn(r);
}

// ---------------- pipelined mma.sync split-bf16 GEMM (+ fused attention scores) ----------------
// 128xNTILE block tile, 4 x WARPS_N warps (256 threads for WARPS_N=2), 2 CTAs/SM.
// SCORES==1 requires WN==64 (warp slab == one head).
template <int KT, int NT, int NTILE, int WARPS_N, int JK, int SCORES>
__global__ __launch_bounds__(128 * WARPS_N, 2)
void mma_gemm_k(const float* __restrict__ A, const float* __restrict__ A2,
                const __nv_bfloat16* __restrict__ Bhi, const __nv_bfloat16* __restrict__ Blo,
                const float* __restrict__ bias, float* __restrict__ C,
                const float* __restrict__ asrc, const float* __restrict__ adst, int M) {
    constexpr int THREADS = 128 * WARPS_N;
    constexpr int WN = NTILE / WARPS_N;
    constexpr int NI = WN / 8;
    constexpr int LDA = 1024 / THREADS;
    constexpr int LDB = 8 * NTILE / THREADS;
    constexpr int CH = KT / 32;
    constexpr unsigned ABUF = 20480;
    constexpr unsigned BOFF = 2 * ABUF;
    constexpr unsigned BBUF = NTILE * 160;

    extern __shared__ char dynsm[];
    unsigned sbase = smem_u32(dynsm);
    int tid = threadIdx.x, lane = tid & 31, wid = tid >> 5;
    int wr = wid & 3, wc = wid >> 2;
    int rowBase = blockIdx.y * 128;
    int colBase = blockIdx.x * NTILE;
    float acc[2][NI][4] = {};
    float4 av[LDA], av2[LDA];

    auto loadA = [&](int c) {
        #pragma unroll
        for (int i = 0; i < LDA; i++) {
            int q = tid + i * THREADS;
            int r = q >> 3, cc = (q & 7) * 4;
            int grow = rowBase + r;
            av[i] = make_float4(0.f, 0.f, 0.f, 0.f);
            av2[i] = make_float4(0.f, 0.f, 0.f, 0.f);
            if (grow < M) {
                av[i] = *(const float4*)(A + (size_t)grow * KT + c * 32 + cc);
                if (JK) av2[i] = *(const float4*)(A2 + (size_t)grow * KT + c * 32 + cc);
            }
        }
    };
    auto storeA = [&](int buf) {
        #pragma unroll
        for (int i = 0; i < LDA; i++) {
            int q = tid + i * THREADS;
            int r = q >> 3, cc = (q & 7) * 4;
            float4 v = av[i];
            if (JK) {
                float4 w = av2[i];
                v.x = fmaxf(v.x, w.x); v.y = fmaxf(v.y, w.y);
                v.z = fmaxf(v.z, w.z); v.w = fmaxf(v.w, w.w);
            }
            float hx = __bfloat162float(__float2bfloat16_rn(v.x));
            float hy = __bfloat162float(__float2bfloat16_rn(v.y));
            float hz = __bfloat162float(__float2bfloat16_rn(v.z));
            float hw = __bfloat162float(__float2bfloat16_rn(v.w));
            unsigned off = buf * ABUF + (unsigned)(r * 40 + cc) * 2;
            *(uint2*)(dynsm + off) = make_uint2(pack2(hx, hy), pack2(hz, hw));
            *(uint2*)(dynsm + off + 10240) =
                make_uint2(pack2(v.x - hx, v.y - hy), pack2(v.z - hz, v.w - hw));
        }
    };
    auto loadB = [&](int c, int buf) {
        #pragma unroll
        for (int i = 0; i < LDB; i++) {
            int q = tid + i * THREADS;
            int hl = q / (4 * NTILE);
            int rem = q - hl * 4 * NTILE;
            int r = rem >> 2, seg = rem & 3;
            const __nv_bfloat16* src = hl ? Blo : Bhi;
            unsigned soff = BOFF + buf * BBUF + hl * (NTILE * 80) +
                            (unsigned)(r * 40 + seg * 8) * 2;
            cp16(sbase + soff, src + (size_t)(colBase + r) * KT + c * 32 + seg * 8);
        }
        asm volatile("cp.async.commit_group;");
    };
    auto compute = [&](int buf) {
        unsigned saA = sbase + buf * ABUF;
        unsigned saB = sbase + BOFF + buf * BBUF;
        #pragma unroll
        for (int kk = 0; kk < 32; kk += 16) {
            unsigned ah[2][4], al[2][4], bh[NI / 2][4], bl[NI / 2][4];
            #pragma unroll
            for (int mi = 0; mi < 2; mi++) {
                int row = wr * 32 + mi * 16 + (lane & 7) + ((lane & 8) ? 8 : 0);
                int col = kk + ((lane & 16) ? 8 : 0);
                ldsm4(ah[mi], saA + (unsigned)(row * 40 + col) * 2);
                ldsm4(al[mi], saA + 10240 + (unsigned)(row * 40 + col) * 2);
            }
            #pragma unroll
            for (int nb = 0; nb < NI / 2; nb++) {
                int row = wc * WN + nb * 16 + ((lane & 16) ? 8 : 0) + (lane & 7);
                int col = kk + ((lane & 8) ? 8 : 0);
                ldsm4(bh[nb], saB + (unsigned)(row * 40 + col) * 2);
                ldsm4(bl[nb], saB + (unsigned)(NTILE * 80) + (unsigned)(row * 40 + col) * 2);
            }
            #pragma unroll
            for (int mi = 0; mi < 2; mi++)
                #pragma unroll
                for (int nb = 0; nb < NI / 2; nb++) {
                    mma16816(acc[mi][2 * nb], ah[mi], &bh[nb][0]);
                    mma16816(acc[mi][2 * nb], ah[mi], &bl[nb][0]);
                    mma16816(acc[mi][2 * nb], al[mi], &bh[nb][0]);
                    mma16816(acc[mi][2 * nb + 1], ah[mi], &bh[nb][2]);
                    mma16816(acc[mi][2 * nb + 1], ah[mi], &bl[nb][2]);
                    mma16816(acc[mi][2 * nb + 1], al[mi], &bh[nb][2]);
                }
        }
    };

    loadB(0, 0);
    loadA(0);
    storeA(0);
    asm volatile("cp.async.wait_group 0;");
    __syncthreads();
    for (int c = 0; c < CH; c++) {
        int buf = c & 1;
        if (c + 1 < CH) { loadB(c + 1, buf ^ 1); loadA(c + 1); }
        compute(buf);
        if (c + 1 < CH) {
            storeA(buf ^ 1);
            asm volatile("cp.async.wait_group 0;");
        }
        __syncthreads();
    }
    #pragma unroll
    for (int mi = 0; mi < 2; mi++) {
        int grow0 = rowBase + wr * 32 + mi * 16 + (lane >> 2);
        int grow1 = grow0 + 8;
        #pragma unroll
        for (int ni = 0; ni < NI; ni++) {
            int gcol = colBase + wc * WN + ni * 8 + (lane & 3) * 2;
            float2 v0 = make_float2(acc[mi][ni][0], acc[mi][ni][1]);
            float2 v1 = make_float2(acc[mi][ni][2], acc[mi][ni][3]);
            if (JK) {
                float b0 = bias[gcol], b1 = bias[gcol + 1];
                v0.x += b0; v0.y += b1; v1.x += b0; v1.y += b1;
            }
            if (grow0 < M) *(float2*)(C + (size_t)grow0 * NT + gcol) = v0;
            if (grow1 < M) *(float2*)(C + (size_t)grow1 * NT + gcol) = v1;
        }
    }
    if (SCORES) {
        int head = (colBase >> 6) + wc;   // WN == 64
        float as[NI][2], ad[NI][2];
        #pragma unroll
        for (int ni = 0; ni < NI; ni++) {
            int c = colBase + wc * WN + ni * 8 + (lane & 3) * 2;
            as[ni][0] = asrc[c]; as[ni][1] = asrc[c + 1];
            ad[ni][0] = adst[c]; ad[ni][1] = adst[c + 1];
        }
        #pragma unroll
        for (int mi = 0; mi < 2; mi++) {
            float e0 = 0.f, e1 = 0.f, d0 = 0.f, d1 = 0.f;
            #pragma unroll
            for (int ni = 0; ni < NI; ni++) {
                e0 = fmaf(acc[mi][ni][0], as[ni][0], e0);
                e0 = fmaf(acc[mi][ni][1], as[ni][1], e0);
                e1 = fmaf(acc[mi][ni][2], as[ni][0], e1);
                e1 = fmaf(acc[mi][ni][3], as[ni][1], e1);
                d0 = fmaf(acc[mi][ni][0], ad[ni][0], d0);
                d0 = fmaf(acc[mi][ni][1], ad[ni][1], d0);
                d1 = fmaf(acc[mi][ni][2], ad[ni][0], d1);
                d1 = fmaf(acc[mi][ni][3], ad[ni][1], d1);
            }
            e0 += __shfl_xor_sync(0xFFFFFFFFu, e0, 1); e0 += __shfl_xor_sync(0xFFFFFFFFu, e0, 2);
            e1 += __shfl_xor_sync(0xFFFFFFFFu, e1, 1); e1 += __shfl_xor_sync(0xFFFFFFFFu, e1, 2);
            d0 += __shfl_xor_sync(0xFFFFFFFFu, d0, 1); d0 += __shfl_xor_sync(0xFFFFFFFFu, d0, 2);
            d1 += __shfl_xor_sync(0xFFFFFFFFu, d1, 1); d1 += __shfl_xor_sync(0xFFFFFFFFu, d1, 2);
            if ((lane & 3) == 0) {
                int r0 = rowBase + wr * 32 + mi * 16 + (lane >> 2);
                int r1 = r0 + 8;
                if (r0 < M) { g_es[r0 * 4 + head] = e0; g_ed[r0 * 4 + head] = d0; }
                if (r1 < M) { g_es[r1 * 4 + head] = e1; g_ed[r1 * 4 + head] = d1; }
            }
        }
    }
}

// ---------------- fused softmax + aggregate (+ optional BN stats): warp per node ----------------
// grid = NN/8 exactly (NN % 8 == 0): every warp owns a node.
template <int BN>
__global__ __launch_bounds__(256)
void softagg_k(const float* __restrict__ hfeat, const float* __restrict__ bias,
               float* __restrict__ out) {
    __shared__ float sal[8][32][4];   // alpha cache / reduction buffer
    int t = threadIdx.x, wid = t >> 5, lane = t & 31;
    int n = blockIdx.x * 8 + wid;
    int s = g_rowstart[n], en = g_rowstart[n + 1];
    int deg = en - s;
    bool small = (deg <= 32);

    // ---- phase 1: softmax ----
    if (deg > 0) {
        float4 ed = *(const float4*)&g_ed[n * 4];
        if (small) {
            float v0 = -1e30f, v1 = -1e30f, v2 = -1e30f, v3 = -1e30f;
            if (lane < deg) {
                int src = g_csr_src[s + lane];
                float4 es = *(const float4*)&g_es[src * 4];
                v0 = es.x + ed.x; v0 = fmaxf(v0, 0.2f * v0);
                v1 = es.y + ed.y; v1 = fmaxf(v1, 0.2f * v1);
                v2 = es.z + ed.z; v2 = fmaxf(v2, 0.2f * v2);
                v3 = es.w + ed.w; v3 = fmaxf(v3, 0.2f * v3);
            }
            float m0 = v0, m1 = v1, m2 = v2, m3 = v3;
            #pragma unroll
            for (int o = 16; o > 0; o >>= 1) {
                m0 = fmaxf(m0, __shfl_xor_sync(0xFFFFFFFFu, m0, o));
                m1 = fmaxf(m1, __shfl_xor_sync(0xFFFFFFFFu, m1, o));
                m2 = fmaxf(m2, __shfl_xor_sync(0xFFFFFFFFu, m2, o));
                m3 = fmaxf(m3, __shfl_xor_sync(0xFFFFFFFFu, m3, o));
            }
            float p0 = 0.f, p1 = 0.f, p2 = 0.f, p3 = 0.f;
            if (lane < deg) {
                p0 = __expf(v0 - m0); p1 = __expf(v1 - m1);
                p2 = __expf(v2 - m2); p3 = __expf(v3 - m3);
            }
            float d0 = p0, d1 = p1, d2 = p2, d3 = p3;
            #pragma unroll
            for (int o = 16; o > 0; o >>= 1) {
                d0 += __shfl_xor_sync(0xFFFFFFFFu, d0, o);
                d1 += __shfl_xor_sync(0xFFFFFFFFu, d1, o);
                d2 += __shfl_xor_sync(0xFFFFFFFFu, d2, o);
                d3 += __shfl_xor_sync(0xFFFFFFFFu, d3, o);
            }
            if (lane < deg) {
                sal[wid][lane][0] = p0 / (d0 + 1e-16f);
                sal[wid][lane][1] = p1 / (d1 + 1e-16f);
                sal[wid][lane][2] = p2 / (d2 + 1e-16f);
                sal[wid][lane][3] = p3 / (d3 + 1e-16f);
            }
        } else {
            float m0 = -1e30f, m1 = -1e30f, m2 = -1e30f, m3 = -1e30f;
            for (int p = s + lane; p < en; p += 32) {
                int src = g_csr_src[p];
                float4 es = *(const float4*)&g_es[src * 4];
                float v0 = es.x + ed.x; v0 = fmaxf(v0, 0.2f * v0);
                float v1 = es.y + ed.y; v1 = fmaxf(v1, 0.2f * v1);
                float v2 = es.z + ed.z; v2 = fmaxf(v2, 0.2f * v2);
                float v3 = es.w + ed.w; v3 = fmaxf(v3, 0.2f * v3);
                m0 = fmaxf(m0, v0); m1 = fmaxf(m1, v1);
                m2 = fmaxf(m2, v2); m3 = fmaxf(m3, v3);
            }
            #pragma unroll
            for (int o = 16; o > 0; o >>= 1) {
                m0 = fmaxf(m0, __shfl_xor_sync(0xFFFFFFFFu, m0, o));
                m1 = fmaxf(m1, __shfl_xor_sync(0xFFFFFFFFu, m1, o));
                m2 = fmaxf(m2, __shfl_xor_sync(0xFFFFFFFFu, m2, o));
                m3 = fmaxf(m3, __shfl_xor_sync(0xFFFFFFFFu, m3, o));
            }
            float d0 = 0.f, d1 = 0.f, d2 = 0.f, d3 = 0.f;
            for (int p = s + lane; p < en; p += 32) {
                int src = g_csr_src[p];
                float4 es = *(const float4*)&g_es[src * 4];
                float v0 = es.x + ed.x; v0 = fmaxf(v0, 0.2f * v0);
                float v1 = es.y + ed.y; v1 = fmaxf(v1, 0.2f * v1);
                float v2 = es.z + ed.z; v2 = fmaxf(v2, 0.2f * v2);
                float v3 = es.w + ed.w; v3 = fmaxf(v3, 0.2f * v3);
                float4 a;
                a.x = __expf(v0 - m0); a.y = __expf(v1 - m1);
                a.z = __expf(v2 - m2); a.w = __expf(v3 - m3);
                d0 += a.x; d1 += a.y; d2 += a.z; d3 += a.w;
                *(float4*)&g_alpha[(size_t)p * 4] = a;
            }
            #pragma unroll
            for (int o = 16; o > 0; o >>= 1) {
                d0 += __shfl_xor_sync(0xFFFFFFFFu, d0, o);
                d1 += __shfl_xor_sync(0xFFFFFFFFu, d1, o);
                d2 += __shfl_xor_sync(0xFFFFFFFFu, d2, o);
                d3 += __shfl_xor_sync(0xFFFFFFFFu, d3, o);
            }
            float i0 = 1.f / (d0 + 1e-16f), i1 = 1.f / (d1 + 1e-16f);
            float i2 = 1.f / (d2 + 1e-16f), i3 = 1.f / (d3 + 1e-16f);
            for (int p = s + lane; p < en; p += 32) {
                float4 a = *(const float4*)&g_alpha[(size_t)p * 4];
                a.x *= i0; a.y *= i1; a.z *= i2; a.w *= i3;
                *(float4*)&g_alpha[(size_t)p * 4] = a;
            }
        }
    }
    __syncwarp();

    // ---- phase 2: aggregate, 4-edge unroll ----
    int h0 = lane >> 4, h1 = h0 + 2;
    int c0 = lane * 4, c1 = 128 + lane * 4;
    float4 A = {0, 0, 0, 0}, B = {0, 0, 0, 0};
    float4 A2 = {0, 0, 0, 0}, B2 = {0, 0, 0, 0};
    int p = s, j = 0;
    for (; p + 4 <= en; p += 4, j += 4) {
        int s0 = g_csr_src[p], s1 = g_csr_src[p + 1];
        int s2 = g_csr_src[p + 2], s3 = g_csr_src[p + 3];
        float w0a, w0b, w1a, w1b, w2a, w2b, w3a, w3b;
        if (small) {
            w0a = sal[wid][j][h0];     w0b = sal[wid][j][h1];
            w1a = sal[wid][j + 1][h0]; w1b = sal[wid][j + 1][h1];
            w2a = sal[wid][j + 2][h0]; w2b = sal[wid][j + 2][h1];
            w3a = sal[wid][j + 3][h0]; w3b = sal[wid][j + 3][h1];
        } else {
            w0a = g_alpha[(size_t)p * 4 + h0];       w0b = g_alpha[(size_t)p * 4 + h1];
            w1a = g_alpha[(size_t)(p + 1) * 4 + h0]; w1b = g_alpha[(size_t)(p + 1) * 4 + h1];
            w2a = g_alpha[(size_t)(p + 2) * 4 + h0]; w2b = g_alpha[(size_t)(p + 2) * 4 + h1];
            w3a = g_alpha[(size_t)(p + 3) * 4 + h0]; w3b = g_alpha[(size_t)(p + 3) * 4 + h1];
        }
        float4 f0a = *(const float4*)(hfeat + (size_t)s0 * HC + c0);
        float4 f0b = *(const float4*)(hfeat + (size_t)s0 * HC + c1);
        float4 f1a = *(const float4*)(hfeat + (size_t)s1 * HC + c0);
        float4 f1b = *(const float4*)(hfeat + (size_t)s1 * HC + c1);
        float4 f2a = *(const float4*)(hfeat + (size_t)s2 * HC + c0);
        float4 f2b = *(const float4*)(hfeat + (size_t)s2 * HC + c1);
        float4 f3a = *(const float4*)(hfeat + (size_t)s3 * HC + c0);
        float4 f3b = *(const float4*)(hfeat + (size_t)s3 * HC + c1);
        A.x = fmaf(w0a, f0a.x, A.x); A.y = fmaf(w0a, f0a.y, A.y);
        A.z = fmaf(w0a, f0a.z, A.z); A.w = fmaf(w0a, f0a.w, A.w);
        B.x = fmaf(w0b, f0b.x, B.x); B.y = fmaf(w0b, f0b.y, B.y);
        B.z = fmaf(w0b, f0b.z, B.z); B.w = fmaf(w0b, f0b.w, B.w);
        A2.x = fmaf(w1a, f1a.x, A2.x); A2.y = fmaf(w1a, f1a.y, A2.y);
        A2.z = fmaf(w1a, f1a.z, A2.z); A2.w = fmaf(w1a, f1a.w, A2.w);
        B2.x = fmaf(w1b, f1b.x, B2.x); B2.y = fmaf(w1b, f1b.y, B2.y);
        B2.z = fmaf(w1b, f1b.z, B2.z); B2.w = fmaf(w1b, f1b.w, B2.w);
        A.x = fmaf(w2a, f2a.x, A.x); A.y = fmaf(w2a, f2a.y, A.y);
        A.z = fmaf(w2a, f2a.z, A.z); A.w = fmaf(w2a, f2a.w, A.w);
        B.x = fmaf(w2b, f2b.x, B.x); B.y = fmaf(w2b, f2b.y, B.y);
        B.z = fmaf(w2b, f2b.z, B.z); B.w = fmaf(w2b, f2b.w, B.w);
        A2.x = fmaf(w3a, f3a.x, A2.x); A2.y = fmaf(w3a, f3a.y, A2.y);
        A2.z = fmaf(w3a, f3a.z, A2.z); A2.w = fmaf(w3a, f3a.w, A2.w);
        B2.x = fmaf(w3b, f3b.x, B2.x); B2.y = fmaf(w3b, f3b.y, B2.y);
        B2.z = fmaf(w3b, f3b.z, B2.z); B2.w = fmaf(w3b, f3b.w, B2.w);
    }
    for (; p < en; p++, j++) {
        int s0 = g_csr_src[p];
        float wa, wb;
        if (small) { wa = sal[wid][j][h0]; wb = sal[wid][j][h1]; }
        else { wa = g_alpha[(size_t)p * 4 + h0]; wb = g_alpha[(size_t)p * 4 + h1]; }
        float4 f0a = *(const float4*)(hfeat + (size_t)s0 * HC + c0);
        float4 f0b = *(const float4*)(hfeat + (size_t)s0 * HC + c1);
        A.x = fmaf(wa, f0a.x, A.x); A.y = fmaf(wa, f0a.y, A.y);
        A.z = fmaf(wa, f0a.z, A.z); A.w = fmaf(wa, f0a.w, A.w);
        B.x = fmaf(wb, f0b.x, B.x); B.y = fmaf(wb, f0b.y, B.y);
        B.z = fmaf(wb, f0b.z, B.z); B.w = fmaf(wb, f0b.w, B.w);
    }
    float4 ba = *(const float4*)(bias + c0);
    float4 bb = *(const float4*)(bias + c1);
    float4 oa, ob;
    oa.x = A.x + A2.x + ba.x; oa.y = A.y + A2.y + ba.y;
    oa.z = A.z + A2.z + ba.z; oa.w = A.w + A2.w + ba.w;
    ob.x = B.x + B2.x + bb.x; ob.y = B.y + B2.y + bb.y;
    ob.z = B.z + B2.z + bb.z; ob.w = B.w + B2.w + bb.w;
    *(float4*)(out + (size_t)n * HC + c0) = oa;
    *(float4*)(out + (size_t)n * HC + c1) = ob;

    // ---- optional BN statistics (block-level reduce, then global atomics) ----
    if (BN) {
        // round 1: oa (channels 0..127)
        __syncthreads();
        sal[wid][lane][0] = oa.x; sal[wid][lane][1] = oa.y;
        sal[wid][lane][2] = oa.z; sal[wid][lane][3] = oa.w;
        __syncthreads();
        if (t < 128) {
            float sum = 0.f, sq = 0.f;
            #pragma unroll
            for (int w = 0; w < 8; w++) {
                float v = sal[w][t >> 2][t & 3];
                sum += v; sq += v * v;
            }
            atomicAdd(&g_bnsum[t], sum);
            atomicAdd(&g_bnsum[HC + t], sq);
        }
        // round 2: ob (channels 128..255)
        __syncthreads();
        sal[wid][lane][0] = ob.x; sal[wid][lane][1] = ob.y;
        sal[wid][lane][2] = ob.z; sal[wid][lane][3] = ob.w;
        __syncthreads();
        if (t < 128) {
            float sum = 0.f, sq = 0.f;
            #pragma unroll
            for (int w = 0; w < 8; w++) {
                float v = sal[w][t >> 2][t & 3];
                sum += v; sq += v * v;
            }
            atomicAdd(&g_bnsum[128 + t], sum);
            atomicAdd(&g_bnsum[HC + 128 + t], sq);
        }
    }
}

// ---------------- BatchNorm apply (stats already in g_bnsum) ----------------
__global__ __launch_bounds__(256)
void bn_apply_k(const float* __restrict__ x, const float* __restrict__ gamma,
                const float* __restrict__ beta, float* __restrict__ y) {
    __shared__ float ssc[HC], ssh[HC];
    int t = threadIdx.x;
    float mean = g_bnsum[t] / (float)NN;
    float var = g_bnsum[HC + t] / (float)NN - mean * mean;
    float sc = gamma[t] * rsqrtf(var + 1e-5f);
    ssc[t] = sc;
    ssh[t] = beta[t] - mean * sc;
    __syncthreads();
    for (long long i = blockIdx.x * 256 + t; i < (long long)NN * 64;
         i += (long long)gridDim.x * 256) {
        int ch = ((int)i & 63) * 4;
        float4 v = *(const float4*)(x + i * 4);
        v.x = v.x * ssc[ch] + ssh[ch];
        v.y = v.y * ssc[ch + 1] + ssh[ch + 1];
        v.z = v.z * ssc[ch + 2] + ssh[ch + 2];
        v.w = v.w * ssc[ch + 3] + ssh[ch + 3];
        v.x = (v.x > 0.f) ? v.x : expm1f(v.x);
        v.y = (v.y > 0.f) ? v.y : expm1f(v.y);
        v.z = (v.z > 0.f) ? v.z : expm1f(v.z);
        v.w = (v.w > 0.f) ? v.w : expm1f(v.w);
        *(float4*)(y + i * 4) = v;
    }
}

// ---------------- host ----------------
#define GDM ((NN + 127) / 128)
#define SMEM_128 (40960 + 2 * 128 * 160)   // 81920
#define SMEM_64  (40960 + 2 * 64 * 160)    // 61440

extern "C" void kernel_launch(void* const* d_in, const int* in_sizes, int n_in,
                              void* d_out, int out_size) {
    const float* x   = (const float*)d_in[0];
    const void*  eidx = d_in[1];
    const float* a1s = (const float*)d_in[3];
    const float* a1d = (const float*)d_in[4];
    const float* b1  = (const float*)d_in[5];
    const float* g1  = (const float*)d_in[6];
    const float* be1 = (const float*)d_in[7];
    const float* a2s = (const float*)d_in[9];
    const float* a2d = (const float*)d_in[10];
    const float* b2  = (const float*)d_in[11];
    const float* lb  = (const float*)d_in[13];
    float* out = (float*)d_out;

    float *ph, *pgat, *pl1, *pl2, *pbn;
    cudaGetSymbolAddress((void**)&ph,   g_h);
    cudaGetSymbolAddress((void**)&pgat, g_gat);
    cudaGetSymbolAddress((void**)&pl1,  g_l1);
    cudaGetSymbolAddress((void**)&pl2,  g_l2);
    cudaGetSymbolAddress((void**)&pbn,  g_bnsum);
    __nv_bfloat16 *w1h, *w1l, *w2h, *w2l, *w3h, *w3l;
    cudaGetSymbolAddress((void**)&w1h, g_w1t_hi);
    cudaGetSymbolAddress((void**)&w1l, g_w1t_lo);
    cudaGetSymbolAddress((void**)&w2h, g_w2t_hi);
    cudaGetSymbolAddress((void**)&w2l, g_w2t_lo);
    cudaGetSymbolAddress((void**)&w3h, g_w3t_hi);
    cudaGetSymbolAddress((void**)&w3l, g_w3t_lo);
    int* ppre;
    cudaGetSymbolAddress((void**)&ppre, g_pre);

    cudaFuncSetAttribute((const void*)mma_gemm_k<FIN, HC, 128, 2, 0, 1>,
                         cudaFuncAttributeMaxDynamicSharedMemorySize, SMEM_128);
    cudaFuncSetAttribute((const void*)mma_gemm_k<HC, HC, 128, 2, 0, 1>,
                         cudaFuncAttributeMaxDynamicSharedMemorySize, SMEM_128);
    cudaFuncSetAttribute((const void*)mma_gemm_k<HC, OUTC, 64, 2, 1, 0>,
                         cudaFuncAttributeMaxDynamicSharedMemorySize, SMEM_64);

    cudaMemsetAsync(ppre, 0, (NN + 2 * SCB) * sizeof(int));
    cudaMemsetAsync(pbn, 0, 2 * HC * sizeof(float));
    detect_k<<<1, 32>>>((const unsigned*)eidx);
    cvt_count_k<<<(EE + 255) / 256, 256>>>(eidx);
    wconv_all_k<<<(FIN * HC + HC * HC + HC * OUTC + 255) / 256, 256>>>(
        (const float*)d_in[2], (const float*)d_in[8], (const float*)d_in[12]);
    {
        dim3 g(2, GDM);
        mma_gemm_k<FIN, HC, 128, 2, 0, 1><<<g, 256, SMEM_128>>>(
            x, nullptr, w1h, w1l, nullptr, ph, a1s, a1d, NN);
    }
    scanfused_k<<<SCB, 256>>>();
    fill_k<<<(EE + 255) / 256, 256>>>();

    softagg_k<1><<<NN / 8, 256>>>(ph, b1, pgat);
    bn_apply_k<<<296, 256>>>(pgat, g1, be1, pl1);

    {
        dim3 g(2, GDM);
        mma_gemm_k<HC, HC, 128, 2, 0, 1><<<g, 256, SMEM_128>>>(
            pl1, nullptr, w2h, w2l, nullptr, ph, a2s, a2d, NN);
    }
    softagg_k<0><<<NN / 8, 256>>>(ph, b2, pl2);

    {
        dim3 g(1, GDM);
        mma_gemm_k<HC, OUTC, 64, 2, 1, 0><<<g, 256, SMEM_64>>>(
            pl1, pl2, w3h, w3l, lb, out, nullptr, nullptr, NN);
    }
}